// round 10
// baseline (speedup 1.0000x reference)
#include <cuda_runtime.h>
#include <cuda_bf16.h>
#include <cstdint>

#define BATCH 8
#define TLEN 256
#define DIM 256
#define NSTEP 12
#define NNEG 100
#define MROWS 2048
#define NCOLS 3072

__device__ float g_C[MROWS * NCOLS];                 // queries for all steps
__device__ __nv_bfloat16 g_tn[MROWS * DIM];          // normalized targets (bf16)
__device__ float g_part[NSTEP * MROWS];              // per-sample loss partials

// ---------------------------------------------------------------------------
// warp reductions (butterfly shfl — f32 redux does NOT exist on sm_103a)
// ---------------------------------------------------------------------------
__device__ __forceinline__ float wsum(float v) {
#pragma unroll
    for (int o = 16; o; o >>= 1) v += __shfl_xor_sync(0xffffffffu, v, o);
    return v;
}
__device__ __forceinline__ float wmax(float v) {
#pragma unroll
    for (int o = 16; o; o >>= 1) v = fmaxf(v, __shfl_xor_sync(0xffffffffu, v, o));
    return v;
}

// ---------------------------------------------------------------------------
// Threefry-2x32 (exact JAX rotation/key schedule)
// ---------------------------------------------------------------------------
__device__ __forceinline__ void tf2x32(uint32_t k0, uint32_t k1,
                                       uint32_t x0, uint32_t x1,
                                       uint32_t &o0, uint32_t &o1) {
    uint32_t ks2 = k0 ^ k1 ^ 0x1BD11BDAu;
    x0 += k0; x1 += k1;
#define TFR(r) { x0 += x1; x1 = __funnelshift_l(x1, x1, (r)); x1 ^= x0; }
    TFR(13) TFR(15) TFR(26) TFR(6)   x0 += k1;  x1 += ks2 + 1u;
    TFR(17) TFR(29) TFR(16) TFR(24)  x0 += ks2; x1 += k0 + 2u;
    TFR(13) TFR(15) TFR(26) TFR(6)   x0 += k0;  x1 += k1 + 3u;
    TFR(17) TFR(29) TFR(16) TFR(24)  x0 += k1;  x1 += ks2 + 4u;
    TFR(13) TFR(15) TFR(26) TFR(6)   x0 += ks2; x1 += k0 + 5u;
#undef TFR
    o0 = x0; o1 = x1;
}

__device__ __forceinline__ uint32_t tf_bits32(uint32_t k0, uint32_t k1, uint32_t i) {
    uint32_t a, b;
    tf2x32(k0, k1, 0u, i, a, b);
    return a ^ b;
}

// ---------------------------------------------------------------------------
// bf16x2 fused multiply-add (elementwise, bf16 accumulate)
// ---------------------------------------------------------------------------
__device__ __forceinline__ void bfma2(uint32_t &acc, uint32_t a, uint32_t b) {
    asm("fma.rn.bf16x2 %0, %1, %2, %3;" : "=r"(acc) : "r"(a), "r"(b), "r"(acc));
}
__device__ __forceinline__ uint32_t f2_to_bf2(float lo, float hi) {
    __nv_bfloat162 p = __floats2bfloat162_rn(lo, hi);   // .x = lo (low half)
    return *reinterpret_cast<uint32_t*>(&p);
}

// ---------------------------------------------------------------------------
// Kernel 1: normalize target rows, store bf16
// ---------------------------------------------------------------------------
__global__ void k_norm_targets(const float* __restrict__ tgt) {
    int gw = (blockIdx.x * blockDim.x + threadIdx.x) >> 5;
    int lane = threadIdx.x & 31;
    if (gw >= BATCH * TLEN) return;
    const float4* r = reinterpret_cast<const float4*>(tgt + (size_t)gw * DIM);
    float4 a = r[lane * 2];
    float4 b = r[lane * 2 + 1];
    float ss = a.x*a.x + a.y*a.y + a.z*a.z + a.w*a.w
             + b.x*b.x + b.y*b.y + b.z*b.z + b.w*b.w;
    ss = wsum(ss);
    float inv = 1.0f / fmaxf(sqrtf(ss), 1e-12f);
    uint4 u;
    u.x = f2_to_bf2(a.x * inv, a.y * inv);
    u.y = f2_to_bf2(a.z * inv, a.w * inv);
    u.z = f2_to_bf2(b.x * inv, b.y * inv);
    u.w = f2_to_bf2(b.z * inv, b.w * inv);
    reinterpret_cast<uint4*>(g_tn + (size_t)gw * DIM)[lane] = u;
}

// ---------------------------------------------------------------------------
// Kernel 2: C[2048,3072] = A[2048,256] * Bw[3072,256]^T (12 step-GEMMs fused)
// ---------------------------------------------------------------------------
__global__ __launch_bounds__(256, 2) void k_gemm(const float* __restrict__ A,
                                                 const float* __restrict__ Bw) {
    __shared__ float As[8][132];
    __shared__ float Bs[8][132];
    int bm = blockIdx.y * 128;
    int bn = blockIdx.x * 128;
    int tid = threadIdx.x;
    int tx = tid & 15, ty = tid >> 4;
    int lr = tid >> 1;
    int lc = (tid & 1) * 4;
    const float* Ag = A + (size_t)(bm + lr) * DIM + lc;
    const float* Bg = Bw + (size_t)(bn + lr) * DIM + lc;
    float acc[8][8];
#pragma unroll
    for (int i = 0; i < 8; i++)
#pragma unroll
        for (int j = 0; j < 8; j++) acc[i][j] = 0.0f;

    for (int k0 = 0; k0 < DIM; k0 += 8) {
        float4 av = *reinterpret_cast<const float4*>(Ag + k0);
        float4 bv = *reinterpret_cast<const float4*>(Bg + k0);
        As[lc + 0][lr] = av.x; As[lc + 1][lr] = av.y;
        As[lc + 2][lr] = av.z; As[lc + 3][lr] = av.w;
        Bs[lc + 0][lr] = bv.x; Bs[lc + 1][lr] = bv.y;
        Bs[lc + 2][lr] = bv.z; Bs[lc + 3][lr] = bv.w;
        __syncthreads();
#pragma unroll
        for (int k = 0; k < 8; k++) {
            float ar[8], br[8];
            *reinterpret_cast<float4*>(&ar[0]) = *reinterpret_cast<const float4*>(&As[k][ty * 4]);
            *reinterpret_cast<float4*>(&ar[4]) = *reinterpret_cast<const float4*>(&As[k][64 + ty * 4]);
            *reinterpret_cast<float4*>(&br[0]) = *reinterpret_cast<const float4*>(&Bs[k][tx * 4]);
            *reinterpret_cast<float4*>(&br[4]) = *reinterpret_cast<const float4*>(&Bs[k][64 + tx * 4]);
#pragma unroll
            for (int i = 0; i < 8; i++)
#pragma unroll
                for (int j = 0; j < 8; j++) acc[i][j] = fmaf(ar[i], br[j], acc[i][j]);
        }
        __syncthreads();
    }
#pragma unroll
    for (int i = 0; i < 8; i++) {
        int m = bm + ((i < 4) ? (ty * 4 + i) : (64 + ty * 4 + i - 4));
        float* cp = g_C + (size_t)m * NCOLS + bn;
        *reinterpret_cast<float4*>(cp + tx * 4) =
            make_float4(acc[i][0], acc[i][1], acc[i][2], acc[i][3]);
        *reinterpret_cast<float4*>(cp + 64 + tx * 4) =
            make_float4(acc[i][4], acc[i][5], acc[i][6], acc[i][7]);
    }
}

// ---------------------------------------------------------------------------
// Kernel 3: add bias + L2-normalize each query row (warp per row)
// ---------------------------------------------------------------------------
__global__ void k_bias_norm(const float* __restrict__ bias) {
    int gw = (blockIdx.x * blockDim.x + threadIdx.x) >> 5;
    int lane = threadIdx.x & 31;
    if (gw >= MROWS * NSTEP) return;
    int m = gw / NSTEP, s = gw % NSTEP;
    float* row = g_C + (size_t)m * NCOLS + (size_t)s * DIM;
    const float4* b4 = reinterpret_cast<const float4*>(bias + (size_t)s * DIM);
    float4 v0 = reinterpret_cast<float4*>(row)[lane * 2];
    float4 v1 = reinterpret_cast<float4*>(row)[lane * 2 + 1];
    float4 c0 = b4[lane * 2];
    float4 c1 = b4[lane * 2 + 1];
    v0.x += c0.x; v0.y += c0.y; v0.z += c0.z; v0.w += c0.w;
    v1.x += c1.x; v1.y += c1.y; v1.z += c1.z; v1.w += c1.w;
    float ss = v0.x*v0.x + v0.y*v0.y + v0.z*v0.z + v0.w*v0.w
             + v1.x*v1.x + v1.y*v1.y + v1.z*v1.z + v1.w*v1.w;
    ss = wsum(ss);
    float inv = 1.0f / fmaxf(sqrtf(ss), 1e-12f);
    v0.x *= inv; v0.y *= inv; v0.z *= inv; v0.w *= inv;
    v1.x *= inv; v1.y *= inv; v1.z *= inv; v1.w *= inv;
    reinterpret_cast<float4*>(row)[lane * 2] = v0;
    reinterpret_cast<float4*>(row)[lane * 2 + 1] = v1;
}

// ---------------------------------------------------------------------------
// Kernel 4: per-(step,b,t) InfoNCE partial loss
//   Half-warp-per-item: each 16-lane group handles one item per iteration
//   (lane covers 32B of the 512B row via 2x LDG.128 + 8 HFMA2), so the warp
//   retires 2 items per iteration and pays clamp/LDS/unpack/loop once.
//   16 partials/item go to smem (stride 17); 101-thread pass reduces them.
// ---------------------------------------------------------------------------
__global__ __launch_bounds__(256) void k_loss() {
    int s = blockIdx.y + 1;           // step 1..12
    int T2 = TLEN - s;
    int bt = blockIdx.x;              // 0..2047
    int b = bt >> 8, t = bt & 255;
    int tid = threadIdx.x;
    __shared__ float sp[101 * 17];    // 16 per-lane partials/item, pad 17
    __shared__ float logits[101];
    __shared__ int sidx[101];         // row * 32 (uint4 units, 512B rows)
    if (t >= T2) {
        if (tid == 0) g_part[(size_t)(s - 1) * MROWS + bt] = 0.0f;
        return;
    }
    uint32_t span = (uint32_t)(BATCH * T2);
    if (tid < 101) {
        int row;
        if (tid == 0) {
            row = b * TLEN + t + s;   // positive
        } else {
            uint32_t k0, k1;
            tf2x32(0u, 1234u, 0u, (uint32_t)s, k0, k1);   // fold_in(key(1234), s)
            uint32_t n = span * NNEG;
            uint32_t i = (uint32_t)((b * T2 + t) * NNEG + (tid - 1));
            uint32_t hi = tf_bits32(k0, k1, i);
            uint32_t lo = tf_bits32(k0, k1, n + i);
            uint32_t m16 = 65536u % span;
            uint32_t mult = (m16 * m16) % span;
            uint32_t off = ((hi % span) * mult + (lo % span)) % span;
            uint32_t b2 = off / (uint32_t)T2;
            uint32_t t2 = off - b2 * (uint32_t)T2;
            row = (int)(b2 * TLEN + (uint32_t)s + t2);
        }
        sidx[tid] = row * 32;
    }
    __syncthreads();

    int lane = tid & 31, w = tid >> 5;
    int half = lane >> 4;             // which item of the pair
    int qoff = lane & 15;             // 32B slice index within the row

    // Query: this lane's 16 contiguous f32 (elements [qoff*16, qoff*16+16))
    // as 8 bf16x2 words.
    const float* qrow = g_C + (size_t)(b * TLEN + t) * NCOLS + (size_t)(s - 1) * DIM;
    const float4* q4 = reinterpret_cast<const float4*>(qrow);
    uint32_t qh[8];
#pragma unroll
    for (int i = 0; i < 4; i++) {
        float4 qv = q4[qoff * 4 + i];
        qh[i * 2]     = f2_to_bf2(qv.x, qv.y);
        qh[i * 2 + 1] = f2_to_bf2(qv.z, qv.w);
    }

    const uint4* tn4 = reinterpret_cast<const uint4*>(g_tn);
#pragma unroll 4
    for (int it = 0; it < 7; it++) {
        int g = it * 16 + (w << 1) + half;   // item id (uniform per half-warp)
        int gc = min(g, 100);
        int base = sidx[gc] + qoff * 2;      // uint4 index of this lane's 32B
        uint4 v0 = __ldg(tn4 + base);
        uint4 v1 = __ldg(tn4 + base + 1);
        uint32_t acc = 0;
        bfma2(acc, v0.x, qh[0]);
        bfma2(acc, v0.y, qh[1]);
        bfma2(acc, v0.z, qh[2]);
        bfma2(acc, v0.w, qh[3]);
        bfma2(acc, v1.x, qh[4]);
        bfma2(acc, v1.y, qh[5]);
        bfma2(acc, v1.z, qh[6]);
        bfma2(acc, v1.w, qh[7]);
        // exact unpack of the bf16x2 accumulator halves
        float part = __uint_as_float(acc << 16)
                   + __uint_as_float(acc & 0xffff0000u);
        if (g < 101) sp[gc * 17 + qoff] = part;   // half-warp-uniform predicate
    }
    __syncthreads();

    // Reduce 16 lane-partials per item (thread i -> item i; stride-17 pad
    // keeps every strided column access conflict-free)
    if (tid < 101) {
        const float* r = sp + tid * 17;
        float s0 = 0.f, s1 = 0.f, s2 = 0.f, s3 = 0.f;
#pragma unroll
        for (int k = 0; k < 16; k += 4) {
            s0 += r[k]; s1 += r[k + 1]; s2 += r[k + 2]; s3 += r[k + 3];
        }
        logits[tid] = ((s0 + s1) + (s2 + s3)) * 10.0f;   // /TEMP
    }
    __syncthreads();

    if (w == 0) {
        float mx = -1e30f;
        for (int i = lane; i < 101; i += 32) mx = fmaxf(mx, logits[i]);
        mx = wmax(mx);
        float sum = 0.0f;
        for (int i = lane; i < 101; i += 32) sum += __expf(logits[i] - mx);
        sum = wsum(sum);
        if (lane == 0) {
            float lse = mx + __logf(sum);
            g_part[(size_t)(s - 1) * MROWS + bt] =
                (lse - logits[0]) / (float)(NSTEP * BATCH * T2);
        }
    }
}

// ---------------------------------------------------------------------------
// Kernel 5: deterministic final reduction
// ---------------------------------------------------------------------------
__global__ void k_reduce(float* __restrict__ out) {
    __shared__ float sm[256];
    int tid = threadIdx.x;
    float s = 0.0f;
    for (int i = tid; i < NSTEP * MROWS; i += 256) s += g_part[i];
    sm[tid] = s;
    __syncthreads();
    for (int o = 128; o; o >>= 1) {
        if (tid < o) sm[tid] += sm[tid + o];
        __syncthreads();
    }
    if (tid == 0) out[0] = sm[0];
}

// ---------------------------------------------------------------------------
extern "C" void kernel_launch(void* const* d_in, const int* in_sizes, int n_in,
                              void* d_out, int out_size) {
    const float* ctx  = (const float*)d_in[0];
    const float* tgt  = (const float*)d_in[1];
    const float* W    = (const float*)d_in[2];
    const float* bias = (const float*)d_in[3];
    float* out = (float*)d_out;

    k_norm_targets<<<(BATCH * TLEN) / 8, 256>>>(tgt);
    k_gemm<<<dim3(NCOLS / 128, MROWS / 128), 256>>>(ctx, W);
    k_bias_norm<<<(MROWS * NSTEP) / 8, 256>>>(bias);
    k_loss<<<dim3(MROWS, NSTEP), 256>>>();
    k_reduce<<<1, 256>>>(out);
}

// round 11
// speedup vs baseline: 1.3168x; 1.3168x over previous
#include <cuda_runtime.h>
#include <cuda_bf16.h>
#include <cstdint>

#define BATCH 8
#define TLEN 256
#define DIM 256
#define NSTEP 12
#define NNEG 100
#define MROWS 2048
#define NCOLS 3072

__device__ float g_C[MROWS * NCOLS];                 // queries for all steps
__device__ __nv_bfloat16 g_tn[MROWS * DIM];          // normalized targets (bf16)
__device__ float g_part[NSTEP * MROWS];              // per-sample loss partials
__device__ uint32_t g_Abf[MROWS * DIM / 2];          // ctx in bf16x2, k-major
__device__ uint32_t g_Bbf[NCOLS * DIM / 2];          // W   in bf16x2, k-major

// ---------------------------------------------------------------------------
// warp reductions (butterfly shfl — f32 redux does NOT exist on sm_103a)
// ---------------------------------------------------------------------------
__device__ __forceinline__ float wsum(float v) {
#pragma unroll
    for (int o = 16; o; o >>= 1) v += __shfl_xor_sync(0xffffffffu, v, o);
    return v;
}
__device__ __forceinline__ float wmax(float v) {
#pragma unroll
    for (int o = 16; o; o >>= 1) v = fmaxf(v, __shfl_xor_sync(0xffffffffu, v, o));
    return v;
}

// ---------------------------------------------------------------------------
// Threefry-2x32 (exact JAX rotation/key schedule)
// ---------------------------------------------------------------------------
__device__ __forceinline__ void tf2x32(uint32_t k0, uint32_t k1,
                                       uint32_t x0, uint32_t x1,
                                       uint32_t &o0, uint32_t &o1) {
    uint32_t ks2 = k0 ^ k1 ^ 0x1BD11BDAu;
    x0 += k0; x1 += k1;
#define TFR(r) { x0 += x1; x1 = __funnelshift_l(x1, x1, (r)); x1 ^= x0; }
    TFR(13) TFR(15) TFR(26) TFR(6)   x0 += k1;  x1 += ks2 + 1u;
    TFR(17) TFR(29) TFR(16) TFR(24)  x0 += ks2; x1 += k0 + 2u;
    TFR(13) TFR(15) TFR(26) TFR(6)   x0 += k0;  x1 += k1 + 3u;
    TFR(17) TFR(29) TFR(16) TFR(24)  x0 += k1;  x1 += ks2 + 4u;
    TFR(13) TFR(15) TFR(26) TFR(6)   x0 += ks2; x1 += k0 + 5u;
#undef TFR
    o0 = x0; o1 = x1;
}

__device__ __forceinline__ uint32_t tf_bits32(uint32_t k0, uint32_t k1, uint32_t i) {
    uint32_t a, b;
    tf2x32(k0, k1, 0u, i, a, b);
    return a ^ b;
}

// ---------------------------------------------------------------------------
// bf16x2 helpers
// ---------------------------------------------------------------------------
__device__ __forceinline__ void bfma2(uint32_t &acc, uint32_t a, uint32_t b) {
    asm("fma.rn.bf16x2 %0, %1, %2, %3;" : "=r"(acc) : "r"(a), "r"(b), "r"(acc));
}
__device__ __forceinline__ uint32_t f2_to_bf2(float lo, float hi) {
    __nv_bfloat162 p = __floats2bfloat162_rn(lo, hi);   // .x = lo (low half)
    return *reinterpret_cast<uint32_t*>(&p);
}

// ---------------------------------------------------------------------------
// Kernel 0: fp32 -> bf16x2 conversion (pairs; n = number of float2 pairs)
// ---------------------------------------------------------------------------
__global__ void k_cvt(const float2* __restrict__ src, uint32_t* __restrict__ dst,
                      int n) {
    int i = blockIdx.x * blockDim.x + threadIdx.x;
    if (i < n) {
        float2 v = src[i];
        dst[i] = f2_to_bf2(v.x, v.y);
    }
}

// ---------------------------------------------------------------------------
// Kernel 1: normalize target rows, store bf16
// ---------------------------------------------------------------------------
__global__ void k_norm_targets(const float* __restrict__ tgt) {
    int gw = (blockIdx.x * blockDim.x + threadIdx.x) >> 5;
    int lane = threadIdx.x & 31;
    if (gw >= BATCH * TLEN) return;
    const float4* r = reinterpret_cast<const float4*>(tgt + (size_t)gw * DIM);
    float4 a = r[lane * 2];
    float4 b = r[lane * 2 + 1];
    float ss = a.x*a.x + a.y*a.y + a.z*a.z + a.w*a.w
             + b.x*b.x + b.y*b.y + b.z*b.z + b.w*b.w;
    ss = wsum(ss);
    float inv = 1.0f / fmaxf(sqrtf(ss), 1e-12f);
    uint4 u;
    u.x = f2_to_bf2(a.x * inv, a.y * inv);
    u.y = f2_to_bf2(a.z * inv, a.w * inv);
    u.z = f2_to_bf2(b.x * inv, b.y * inv);
    u.w = f2_to_bf2(b.z * inv, b.w * inv);
    reinterpret_cast<uint4*>(g_tn + (size_t)gw * DIM)[lane] = u;
}

// ---------------------------------------------------------------------------
// Kernel 2: C[2048,3072] = A[2048,256] * B[3072,256]^T via bf16 HMMA
//   mma.sync.m16n8k16, f32 accumulate. Warp tile 32x32 (2 m-frags x 4
//   n-frags). Fragments load directly from k-major bf16x2 global words
//   (pair (k,k+1) at fixed row == one aligned b32). L2 holds A+B (2.5MB).
// ---------------------------------------------------------------------------
__device__ __forceinline__ void mma_bf16(float* d, uint32_t a0, uint32_t a1,
                                         uint32_t a2, uint32_t a3,
                                         uint32_t b0, uint32_t b1) {
    asm("mma.sync.aligned.m16n8k16.row.col.f32.bf16.bf16.f32 "
        "{%0,%1,%2,%3}, {%4,%5,%6,%7}, {%8,%9}, {%0,%1,%2,%3};"
        : "+f"(d[0]), "+f"(d[1]), "+f"(d[2]), "+f"(d[3])
        : "r"(a0), "r"(a1), "r"(a2), "r"(a3), "r"(b0), "r"(b1));
}

__global__ __launch_bounds__(256) void k_mma() {
    int gw = (blockIdx.x * 256 + threadIdx.x) >> 5;   // 0..6143
    int lane = threadIdx.x & 31;
    int wm = gw / (NCOLS / 32);                       // 0..63  (32-row strip)
    int wn = gw % (NCOLS / 32);                       // 0..95  (32-col strip)
    int qr = lane >> 2;                               // 0..7
    int kc = lane & 3;                                // 0..3

    const uint32_t* A = g_Abf;                        // [2048][128] u32
    const uint32_t* B = g_Bbf;                        // [3072][128] u32
    int ar0 = wm * 32 + qr;                           // A rows: ar0, +8, +16, +24
    int bn0 = wn * 32 + qr;                           // B cols: bn0, +8, +16, +24

    float acc[8][4];                                  // [m-frag*4 + n-frag][4]
#pragma unroll
    for (int i = 0; i < 8; i++)
#pragma unroll
        for (int j = 0; j < 4; j++) acc[i][j] = 0.0f;

    const uint32_t* Ap0 = A + (size_t)ar0 * 128 + kc;
    const uint32_t* Ap1 = Ap0 + 8 * 128;
    const uint32_t* Ap2 = Ap0 + 16 * 128;
    const uint32_t* Ap3 = Ap0 + 24 * 128;
    const uint32_t* Bp0 = B + (size_t)bn0 * 128 + kc;
    const uint32_t* Bp1 = Bp0 + 8 * 128;
    const uint32_t* Bp2 = Bp0 + 16 * 128;
    const uint32_t* Bp3 = Bp0 + 24 * 128;

#pragma unroll 4
    for (int kt = 0; kt < 16; kt++) {
        int ko = kt * 8;
        // A fragments for 2 m-tiles (rows ar0.. and ar0+16..)
        uint32_t a00 = Ap0[ko], a01 = Ap1[ko], a02 = Ap0[ko + 4], a03 = Ap1[ko + 4];
        uint32_t a10 = Ap2[ko], a11 = Ap3[ko], a12 = Ap2[ko + 4], a13 = Ap3[ko + 4];
        // B fragments for 4 n-tiles
        uint32_t b00 = Bp0[ko], b01 = Bp0[ko + 4];
        uint32_t b10 = Bp1[ko], b11 = Bp1[ko + 4];
        uint32_t b20 = Bp2[ko], b21 = Bp2[ko + 4];
        uint32_t b30 = Bp3[ko], b31 = Bp3[ko + 4];
        mma_bf16(acc[0], a00, a01, a02, a03, b00, b01);
        mma_bf16(acc[1], a00, a01, a02, a03, b10, b11);
        mma_bf16(acc[2], a00, a01, a02, a03, b20, b21);
        mma_bf16(acc[3], a00, a01, a02, a03, b30, b31);
        mma_bf16(acc[4], a10, a11, a12, a13, b00, b01);
        mma_bf16(acc[5], a10, a11, a12, a13, b10, b11);
        mma_bf16(acc[6], a10, a11, a12, a13, b20, b21);
        mma_bf16(acc[7], a10, a11, a12, a13, b30, b31);
    }

    // Epilogue: D[tid/4][2*(tid%4)], +1; rows +8 for c2/c3. float2 stores.
#pragma unroll
    for (int mf = 0; mf < 2; mf++) {
#pragma unroll
        for (int nf = 0; nf < 4; nf++) {
            float* d = acc[mf * 4 + nf];
            int r = wm * 32 + mf * 16 + qr;
            int c = wn * 32 + nf * 8 + kc * 2;
            *reinterpret_cast<float2*>(g_C + (size_t)r * NCOLS + c) =
                make_float2(d[0], d[1]);
            *reinterpret_cast<float2*>(g_C + (size_t)(r + 8) * NCOLS + c) =
                make_float2(d[2], d[3]);
        }
    }
}

// ---------------------------------------------------------------------------
// Kernel 3: add bias + L2-normalize each query row (warp per row)
// ---------------------------------------------------------------------------
__global__ void k_bias_norm(const float* __restrict__ bias) {
    int gw = (blockIdx.x * blockDim.x + threadIdx.x) >> 5;
    int lane = threadIdx.x & 31;
    if (gw >= MROWS * NSTEP) return;
    int m = gw / NSTEP, s = gw % NSTEP;
    float* row = g_C + (size_t)m * NCOLS + (size_t)s * DIM;
    const float4* b4 = reinterpret_cast<const float4*>(bias + (size_t)s * DIM);
    float4 v0 = reinterpret_cast<float4*>(row)[lane * 2];
    float4 v1 = reinterpret_cast<float4*>(row)[lane * 2 + 1];
    float4 c0 = b4[lane * 2];
    float4 c1 = b4[lane * 2 + 1];
    v0.x += c0.x; v0.y += c0.y; v0.z += c0.z; v0.w += c0.w;
    v1.x += c1.x; v1.y += c1.y; v1.z += c1.z; v1.w += c1.w;
    float ss = v0.x*v0.x + v0.y*v0.y + v0.z*v0.z + v0.w*v0.w
             + v1.x*v1.x + v1.y*v1.y + v1.z*v1.z + v1.w*v1.w;
    ss = wsum(ss);
    float inv = 1.0f / fmaxf(sqrtf(ss), 1e-12f);
    v0.x *= inv; v0.y *= inv; v0.z *= inv; v0.w *= inv;
    v1.x *= inv; v1.y *= inv; v1.z *= inv; v1.w *= inv;
    reinterpret_cast<float4*>(row)[lane * 2] = v0;
    reinterpret_cast<float4*>(row)[lane * 2 + 1] = v1;
}

// ---------------------------------------------------------------------------
// Kernel 4: per-(step,b,t) InfoNCE partial loss (R9 structure: warp-per-item,
//   contiguous 512B row per warp-load = 16 sectors; bf16x2 FMA dot; smem
//   partial reduce). sidx padded to 104 so the item loop has no clamp.
// ---------------------------------------------------------------------------
__global__ __launch_bounds__(256) void k_loss() {
    int s = blockIdx.y + 1;           // step 1..12
    int T2 = TLEN - s;
    int bt = blockIdx.x;              // 0..2047
    int b = bt >> 8, t = bt & 255;
    int tid = threadIdx.x;
    __shared__ float sp[101 * 33];    // per-lane partials, stride 33 (pad)
    __shared__ float logits[101];
    __shared__ int sidx[104];         // row * 32 (uint4 units); 101..103 = pad
    if (t >= T2) {
        if (tid == 0) g_part[(size_t)(s - 1) * MROWS + bt] = 0.0f;
        return;
    }
    uint32_t span = (uint32_t)(BATCH * T2);
    if (tid < 104) {
        int row = 0;                  // pad rows -> row 0 (discarded)
        if (tid == 0) {
            row = b * TLEN + t + s;   // positive
        } else if (tid < 101) {
            uint32_t k0, k1;
            tf2x32(0u, 1234u, 0u, (uint32_t)s, k0, k1);   // fold_in(key(1234), s)
            uint32_t n = span * NNEG;
            uint32_t i = (uint32_t)((b * T2 + t) * NNEG + (tid - 1));
            uint32_t hi = tf_bits32(k0, k1, i);
            uint32_t lo = tf_bits32(k0, k1, n + i);
            uint32_t m16 = 65536u % span;
            uint32_t mult = (m16 * m16) % span;
            uint32_t off = ((hi % span) * mult + (lo % span)) % span;
            uint32_t b2 = off / (uint32_t)T2;
            uint32_t t2 = off - b2 * (uint32_t)T2;
            row = (int)(b2 * TLEN + (uint32_t)s + t2);
        }
        sidx[tid] = row * 32;
    }
    __syncthreads();

    int lane = tid & 31, w = tid >> 5;

    // Query: this lane's 8 contiguous f32 -> 4 bf16x2 words
    const float* qrow = g_C + (size_t)(b * TLEN + t) * NCOLS + (size_t)(s - 1) * DIM;
    const float4* q4 = reinterpret_cast<const float4*>(qrow);
    float4 qa = q4[lane * 2];
    float4 qb = q4[lane * 2 + 1];
    uint32_t qh0 = f2_to_bf2(qa.x, qa.y);
    uint32_t qh1 = f2_to_bf2(qa.z, qa.w);
    uint32_t qh2 = f2_to_bf2(qb.x, qb.y);
    uint32_t qh3 = f2_to_bf2(qb.z, qb.w);

    const uint4* tn4 = reinterpret_cast<const uint4*>(g_tn);
#pragma unroll 4
    for (int it = 0; it < 13; it++) {
        int g = it * 8 + w;           // item id 0..103; uniform across warp
        uint4 v = __ldg(tn4 + sidx[g] + lane);
        uint32_t acc = 0;
        bfma2(acc, v.x, qh0);
        bfma2(acc, v.y, qh1);
        bfma2(acc, v.z, qh2);
        bfma2(acc, v.w, qh3);
        // exact unpack of the bf16x2 accumulator halves
        float part = __uint_as_float(acc << 16)
                   + __uint_as_float(acc & 0xffff0000u);
        if (g < 101) sp[g * 33 + lane] = part;   // warp-uniform predicate
    }
    __syncthreads();

    // Reduce 32 lane-partials per item (thread i -> item i; conflict-free
    // thanks to the stride-33 padding)
    if (tid < 101) {
        const float* r = sp + tid * 33;
        float s0 = 0.f, s1 = 0.f, s2 = 0.f, s3 = 0.f;
#pragma unroll
        for (int k = 0; k < 32; k += 4) {
            s0 += r[k]; s1 += r[k + 1]; s2 += r[k + 2]; s3 += r[k + 3];
        }
        logits[tid] = ((s0 + s1) + (s2 + s3)) * 10.0f;   // /TEMP
    }
    __syncthreads();

    if (w == 0) {
        float mx = -1e30f;
        for (int i = lane; i < 101; i += 32) mx = fmaxf(mx, logits[i]);
        mx = wmax(mx);
        float sum = 0.0f;
        for (int i = lane; i < 101; i += 32) sum += __expf(logits[i] - mx);
        sum = wsum(sum);
        if (lane == 0) {
            float lse = mx + __logf(sum);
            g_part[(size_t)(s - 1) * MROWS + bt] =
                (lse - logits[0]) / (float)(NSTEP * BATCH * T2);
        }
    }
}

// ---------------------------------------------------------------------------
// Kernel 5: deterministic final reduction
// ---------------------------------------------------------------------------
__global__ void k_reduce(float* __restrict__ out) {
    __shared__ float sm[256];
    int tid = threadIdx.x;
    float s = 0.0f;
    for (int i = tid; i < NSTEP * MROWS; i += 256) s += g_part[i];
    sm[tid] = s;
    __syncthreads();
    for (int o = 128; o; o >>= 1) {
        if (tid < o) sm[tid] += sm[tid + o];
        __syncthreads();
    }
    if (tid == 0) out[0] = sm[0];
}

// ---------------------------------------------------------------------------
extern "C" void kernel_launch(void* const* d_in, const int* in_sizes, int n_in,
                              void* d_out, int out_size) {
    const float* ctx  = (const float*)d_in[0];
    const float* tgt  = (const float*)d_in[1];
    const float* W    = (const float*)d_in[2];
    const float* bias = (const float*)d_in[3];
    float* out = (float*)d_out;

    uint32_t* abf;  cudaGetSymbolAddress((void**)&abf, g_Abf);
    uint32_t* bbf;  cudaGetSymbolAddress((void**)&bbf, g_Bbf);

    k_norm_targets<<<(BATCH * TLEN) / 8, 256>>>(tgt);
    k_cvt<<<(MROWS * DIM / 2) / 256, 256>>>((const float2*)ctx, abf, MROWS * DIM / 2);
    k_cvt<<<(NCOLS * DIM / 2) / 256, 256>>>((const float2*)W, bbf, NCOLS * DIM / 2);
    k_mma<<<(MROWS / 32) * (NCOLS / 32) / 8, 256>>>();
    k_bias_norm<<<(MROWS * NSTEP) / 8, 256>>>(bias);
    k_loss<<<dim3(MROWS, NSTEP), 256>>>();
    k_reduce<<<1, 256>>>(out);
}

// round 12
// speedup vs baseline: 1.6218x; 1.2316x over previous
#include <cuda_runtime.h>
#include <cuda_bf16.h>
#include <cstdint>

#define BATCH 8
#define TLEN 256
#define DIM 256
#define NSTEP 12
#define NNEG 100
#define MROWS 2048
#define NCOLS 3072

__device__ float g_C[MROWS * NCOLS];                 // queries for all steps
__device__ __nv_bfloat16 g_tn[MROWS * DIM];          // normalized targets (bf16)
__device__ float g_part[NSTEP * MROWS];              // per-sample loss partials
__device__ uint32_t g_Abf[MROWS * DIM / 2];          // ctx in bf16x2, k-major
__device__ uint32_t g_Bbf[NCOLS * DIM / 2];          // W   in bf16x2, k-major

// ---------------------------------------------------------------------------
// warp reductions (butterfly shfl — f32 redux does NOT exist on sm_103a)
// ---------------------------------------------------------------------------
__device__ __forceinline__ float wsum(float v) {
#pragma unroll
    for (int o = 16; o; o >>= 1) v += __shfl_xor_sync(0xffffffffu, v, o);
    return v;
}
__device__ __forceinline__ float wmax(float v) {
#pragma unroll
    for (int o = 16; o; o >>= 1) v = fmaxf(v, __shfl_xor_sync(0xffffffffu, v, o));
    return v;
}

// ---------------------------------------------------------------------------
// Threefry-2x32 (exact JAX rotation/key schedule)
// ---------------------------------------------------------------------------
__device__ __forceinline__ void tf2x32(uint32_t k0, uint32_t k1,
                                       uint32_t x0, uint32_t x1,
                                       uint32_t &o0, uint32_t &o1) {
    uint32_t ks2 = k0 ^ k1 ^ 0x1BD11BDAu;
    x0 += k0; x1 += k1;
#define TFR(r) { x0 += x1; x1 = __funnelshift_l(x1, x1, (r)); x1 ^= x0; }
    TFR(13) TFR(15) TFR(26) TFR(6)   x0 += k1;  x1 += ks2 + 1u;
    TFR(17) TFR(29) TFR(16) TFR(24)  x0 += ks2; x1 += k0 + 2u;
    TFR(13) TFR(15) TFR(26) TFR(6)   x0 += k0;  x1 += k1 + 3u;
    TFR(17) TFR(29) TFR(16) TFR(24)  x0 += k1;  x1 += ks2 + 4u;
    TFR(13) TFR(15) TFR(26) TFR(6)   x0 += ks2; x1 += k0 + 5u;
#undef TFR
    o0 = x0; o1 = x1;
}

__device__ __forceinline__ uint32_t tf_bits32(uint32_t k0, uint32_t k1, uint32_t i) {
    uint32_t a, b;
    tf2x32(k0, k1, 0u, i, a, b);
    return a ^ b;
}

// ---------------------------------------------------------------------------
// bf16x2 helpers
// ---------------------------------------------------------------------------
__device__ __forceinline__ void bfma2(uint32_t &acc, uint32_t a, uint32_t b) {
    asm("fma.rn.bf16x2 %0, %1, %2, %3;" : "=r"(acc) : "r"(a), "r"(b), "r"(acc));
}
__device__ __forceinline__ uint32_t f2_to_bf2(float lo, float hi) {
    __nv_bfloat162 p = __floats2bfloat162_rn(lo, hi);   // .x = lo (low half)
    return *reinterpret_cast<uint32_t*>(&p);
}

// ---------------------------------------------------------------------------
// async copy / ldmatrix / mma primitives
// ---------------------------------------------------------------------------
__device__ __forceinline__ void cpa16(uint32_t dst, const void* src) {
    asm volatile("cp.async.cg.shared.global [%0], [%1], 16;"
                 :: "r"(dst), "l"(src));
}
__device__ __forceinline__ void ldsm4(uint32_t &r0, uint32_t &r1,
                                      uint32_t &r2, uint32_t &r3, uint32_t a) {
    asm volatile("ldmatrix.sync.aligned.m8n8.x4.shared.b16 {%0,%1,%2,%3}, [%4];"
                 : "=r"(r0), "=r"(r1), "=r"(r2), "=r"(r3) : "r"(a));
}
__device__ __forceinline__ void mma_bf16(float* d, const uint32_t* a,
                                         uint32_t b0, uint32_t b1) {
    asm("mma.sync.aligned.m16n8k16.row.col.f32.bf16.bf16.f32 "
        "{%0,%1,%2,%3}, {%4,%5,%6,%7}, {%8,%9}, {%0,%1,%2,%3};"
        : "+f"(d[0]), "+f"(d[1]), "+f"(d[2]), "+f"(d[3])
        : "r"(a[0]), "r"(a[1]), "r"(a[2]), "r"(a[3]), "r"(b0), "r"(b1));
}

// ---------------------------------------------------------------------------
// Kernel 0: fp32 -> bf16x2 conversion (pairs; n = number of float2 pairs)
// ---------------------------------------------------------------------------
__global__ void k_cvt(const float2* __restrict__ src, uint32_t* __restrict__ dst,
                      int n) {
    int i = blockIdx.x * blockDim.x + threadIdx.x;
    if (i < n) {
        float2 v = src[i];
        dst[i] = f2_to_bf2(v.x, v.y);
    }
}

// ---------------------------------------------------------------------------
// Kernel 1: normalize target rows, store bf16
// ---------------------------------------------------------------------------
__global__ void k_norm_targets(const float* __restrict__ tgt) {
    int gw = (blockIdx.x * blockDim.x + threadIdx.x) >> 5;
    int lane = threadIdx.x & 31;
    if (gw >= BATCH * TLEN) return;
    const float4* r = reinterpret_cast<const float4*>(tgt + (size_t)gw * DIM);
    float4 a = r[lane * 2];
    float4 b = r[lane * 2 + 1];
    float ss = a.x*a.x + a.y*a.y + a.z*a.z + a.w*a.w
             + b.x*b.x + b.y*b.y + b.z*b.z + b.w*b.w;
    ss = wsum(ss);
    float inv = 1.0f / fmaxf(sqrtf(ss), 1e-12f);
    uint4 u;
    u.x = f2_to_bf2(a.x * inv, a.y * inv);
    u.y = f2_to_bf2(a.z * inv, a.w * inv);
    u.z = f2_to_bf2(b.x * inv, b.y * inv);
    u.w = f2_to_bf2(b.z * inv, b.w * inv);
    reinterpret_cast<uint4*>(g_tn + (size_t)gw * DIM)[lane] = u;
}

// ---------------------------------------------------------------------------
// Kernel 2: C[2048,3072] = A[2048,256] * B[3072,256]^T via smem-tiled HMMA.
//   Block tile 128x128, 8 warps (warp = 32x64), K chunks of 32, double-
//   buffered cp.async.cg, fragments via ldmatrix.x4. Smem rows padded to
//   80B -> LDSM 8-row address sets hit 8 distinct 16B slots (conflict-free).
// ---------------------------------------------------------------------------
#define KCHUNKS 8
#define ROWB 80                      // padded row stride in bytes (32 bf16 + pad)
#define TILEB (128 * ROWB)           // 10240 B per tile buffer

__global__ __launch_bounds__(256) void k_mma() {
    __shared__ uint8_t sA[2][TILEB];
    __shared__ uint8_t sB[2][TILEB];

    int tid = threadIdx.x;
    int lane = tid & 31, w = tid >> 5;
    int bm = blockIdx.y * 128;       // M block
    int bn = blockIdx.x * 128;       // N block
    int wmo = (w & 3) * 32;          // warp m-offset in tile
    int wno = (w >> 2) * 64;         // warp n-offset in tile

    uint32_t sAu = (uint32_t)__cvta_generic_to_shared(&sA[0][0]);
    uint32_t sBu = (uint32_t)__cvta_generic_to_shared(&sB[0][0]);

    // copy indexing: 2 rows per thread per tile (128 rows x 4 segs of 16B)
    int crow = tid >> 2, cseg = tid & 3;
    const uint32_t* gA = g_Abf + (size_t)(bm + crow) * 128 + cseg * 4;
    const uint32_t* gB = g_Bbf + (size_t)(bn + crow) * 128 + cseg * 4;
    uint32_t dA = sAu + crow * ROWB + cseg * 16;
    uint32_t dB = sBu + crow * ROWB + cseg * 16;

#define COPY_CHUNK(c, buf)                                                    \
    {                                                                         \
        cpa16(dA + (buf) * TILEB, gA + (c) * 16);                             \
        cpa16(dA + (buf) * TILEB + 64 * ROWB, gA + 64 * 128 + (c) * 16);      \
        cpa16(dB + (buf) * TILEB, gB + (c) * 16);                            \
        cpa16(dB + (buf) * TILEB + 64 * ROWB, gB + 64 * 128 + (c) * 16);      \
        asm volatile("cp.async.commit_group;");                               \
    }

    float acc[2][8][4];
#pragma unroll
    for (int i = 0; i < 2; i++)
#pragma unroll
        for (int j = 0; j < 8; j++)
#pragma unroll
            for (int k = 0; k < 4; k++) acc[i][j][k] = 0.0f;

    int gh = (lane >> 3) & 1;        // ldmatrix address group: row half
    int kh = lane >> 4;              // ldmatrix address group: k half
    int lr = lane & 7;               // row within 8
    int qr = lane >> 2, kc = lane & 3;

    COPY_CHUNK(0, 0)

    for (int c = 0; c < KCHUNKS; c++) {
        int buf = c & 1;
        if (c < KCHUNKS - 1) COPY_CHUNK(c + 1, buf ^ 1)
        if (c < KCHUNKS - 1) asm volatile("cp.async.wait_group 1;");
        else                 asm volatile("cp.async.wait_group 0;");
        __syncthreads();

        uint32_t aBase = sAu + buf * TILEB;
        uint32_t bBase = sBu + buf * TILEB;
#pragma unroll
        for (int c16 = 0; c16 < 2; c16++) {
            uint32_t kbyte = c16 * 32 + kh * 16;
            uint32_t a[2][4];
#pragma unroll
            for (int mf = 0; mf < 2; mf++) {
                uint32_t addr = aBase + (wmo + mf * 16 + gh * 8 + lr) * ROWB + kbyte;
                ldsm4(a[mf][0], a[mf][1], a[mf][2], a[mf][3], addr);
            }
#pragma unroll
            for (int nfp = 0; nfp < 4; nfp++) {
                uint32_t b0, b1, b2, b3;
                uint32_t addr = bBase + (wno + nfp * 16 + gh * 8 + lr) * ROWB + kbyte;
                ldsm4(b0, b1, b2, b3, addr);
                mma_bf16(acc[0][nfp * 2],     a[0], b0, b2);
                mma_bf16(acc[0][nfp * 2 + 1], a[0], b1, b3);
                mma_bf16(acc[1][nfp * 2],     a[1], b0, b2);
                mma_bf16(acc[1][nfp * 2 + 1], a[1], b1, b3);
            }
        }
        __syncthreads();
    }
#undef COPY_CHUNK

    // Epilogue: D row r: c0,c1 at (qr, 2kc); c2,c3 at row +8. float2 stores.
#pragma unroll
    for (int mf = 0; mf < 2; mf++) {
#pragma unroll
        for (int nf = 0; nf < 8; nf++) {
            float* d = acc[mf][nf];
            int r = bm + wmo + mf * 16 + qr;
            int cc = bn + wno + nf * 8 + kc * 2;
            *reinterpret_cast<float2*>(g_C + (size_t)r * NCOLS + cc) =
                make_float2(d[0], d[1]);
            *reinterpret_cast<float2*>(g_C + (size_t)(r + 8) * NCOLS + cc) =
                make_float2(d[2], d[3]);
        }
    }
}

// ---------------------------------------------------------------------------
// Kernel 3: add bias + L2-normalize each query row (warp per row)
// ---------------------------------------------------------------------------
__global__ void k_bias_norm(const float* __restrict__ bias) {
    int gw = (blockIdx.x * blockDim.x + threadIdx.x) >> 5;
    int lane = threadIdx.x & 31;
    if (gw >= MROWS * NSTEP) return;
    int m = gw / NSTEP, s = gw % NSTEP;
    float* row = g_C + (size_t)m * NCOLS + (size_t)s * DIM;
    const float4* b4 = reinterpret_cast<const float4*>(bias + (size_t)s * DIM);
    float4 v0 = reinterpret_cast<float4*>(row)[lane * 2];
    float4 v1 = reinterpret_cast<float4*>(row)[lane * 2 + 1];
    float4 c0 = b4[lane * 2];
    float4 c1 = b4[lane * 2 + 1];
    v0.x += c0.x; v0.y += c0.y; v0.z += c0.z; v0.w += c0.w;
    v1.x += c1.x; v1.y += c1.y; v1.z += c1.z; v1.w += c1.w;
    float ss = v0.x*v0.x + v0.y*v0.y + v0.z*v0.z + v0.w*v0.w
             + v1.x*v1.x + v1.y*v1.y + v1.z*v1.z + v1.w*v1.w;
    ss = wsum(ss);
    float inv = 1.0f / fmaxf(sqrtf(ss), 1e-12f);
    v0.x *= inv; v0.y *= inv; v0.z *= inv; v0.w *= inv;
    v1.x *= inv; v1.y *= inv; v1.z *= inv; v1.w *= inv;
    reinterpret_cast<float4*>(row)[lane * 2] = v0;
    reinterpret_cast<float4*>(row)[lane * 2 + 1] = v1;
}

// ---------------------------------------------------------------------------
// Kernel 4: per-(step,b,t) InfoNCE partial loss (warp-per-item, contiguous
//   512B row per warp-load; bf16x2 FMA dot; smem partial reduce; sidx
//   padded to 104 so the item loop has no clamp)
// ---------------------------------------------------------------------------
__global__ __launch_bounds__(256) void k_loss() {
    int s = blockIdx.y + 1;           // step 1..12
    int T2 = TLEN - s;
    int bt = blockIdx.x;              // 0..2047
    int b = bt >> 8, t = bt & 255;
    int tid = threadIdx.x;
    __shared__ float sp[101 * 33];    // per-lane partials, stride 33 (pad)
    __shared__ float logits[101];
    __shared__ int sidx[104];         // row * 32 (uint4 units); 101..103 = pad
    if (t >= T2) {
        if (tid == 0) g_part[(size_t)(s - 1) * MROWS + bt] = 0.0f;
        return;
    }
    uint32_t span = (uint32_t)(BATCH * T2);
    if (tid < 104) {
        int row = 0;                  // pad rows -> row 0 (discarded)
        if (tid == 0) {
            row = b * TLEN + t + s;   // positive
        } else if (tid < 101) {
            uint32_t k0, k1;
            tf2x32(0u, 1234u, 0u, (uint32_t)s, k0, k1);   // fold_in(key(1234), s)
            uint32_t n = span * NNEG;
            uint32_t i = (uint32_t)((b * T2 + t) * NNEG + (tid - 1));
            uint32_t hi = tf_bits32(k0, k1, i);
            uint32_t lo = tf_bits32(k0, k1, n + i);
            uint32_t m16 = 65536u % span;
            uint32_t mult = (m16 * m16) % span;
            uint32_t off = ((hi % span) * mult + (lo % span)) % span;
            uint32_t b2 = off / (uint32_t)T2;
            uint32_t t2 = off - b2 * (uint32_t)T2;
            row = (int)(b2 * TLEN + (uint32_t)s + t2);
        }
        sidx[tid] = row * 32;
    }
    __syncthreads();

    int lane = tid & 31, w = tid >> 5;

    // Query: this lane's 8 contiguous f32 -> 4 bf16x2 words
    const float* qrow = g_C + (size_t)(b * TLEN + t) * NCOLS + (size_t)(s - 1) * DIM;
    const float4* q4 = reinterpret_cast<const float4*>(qrow);
    float4 qa = q4[lane * 2];
    float4 qb = q4[lane * 2 + 1];
    uint32_t qh0 = f2_to_bf2(qa.x, qa.y);
    uint32_t qh1 = f2_to_bf2(qa.z, qa.w);
    uint32_t qh2 = f2_to_bf2(qb.x, qb.y);
    uint32_t qh3 = f2_to_bf2(qb.z, qb.w);

    const uint4* tn4 = reinterpret_cast<const uint4*>(g_tn);
#pragma unroll 4
    for (int it = 0; it < 13; it++) {
        int g = it * 8 + w;           // item id 0..103; uniform across warp
        uint4 v = __ldg(tn4 + sidx[g] + lane);
        uint32_t acc = 0;
        bfma2(acc, v.x, qh0);
        bfma2(acc, v.y, qh1);
        bfma2(acc, v.z, qh2);
        bfma2(acc, v.w, qh3);
        // exact unpack of the bf16x2 accumulator halves
        float part = __uint_as_float(acc << 16)
                   + __uint_as_float(acc & 0xffff0000u);
        if (g < 101) sp[g * 33 + lane] = part;   // warp-uniform predicate
    }
    __syncthreads();

    // Reduce 32 lane-partials per item (thread i -> item i; conflict-free
    // thanks to the stride-33 padding)
    if (tid < 101) {
        const float* r = sp + tid * 33;
        float s0 = 0.f, s1 = 0.f, s2 = 0.f, s3 = 0.f;
#pragma unroll
        for (int k = 0; k < 32; k += 4) {
            s0 += r[k]; s1 += r[k + 1]; s2 += r[k + 2]; s3 += r[k + 3];
        }
        logits[tid] = ((s0 + s1) + (s2 + s3)) * 10.0f;   // /TEMP
    }
    __syncthreads();

    if (w == 0) {
        float mx = -1e30f;
        for (int i = lane; i < 101; i += 32) mx = fmaxf(mx, logits[i]);
        mx = wmax(mx);
        float sum = 0.0f;
        for (int i = lane; i < 101; i += 32) sum += __expf(logits[i] - mx);
        sum = wsum(sum);
        if (lane == 0) {
            float lse = mx + __logf(sum);
            g_part[(size_t)(s - 1) * MROWS + bt] =
                (lse - logits[0]) / (float)(NSTEP * BATCH * T2);
        }
    }
}

// ---------------------------------------------------------------------------
// Kernel 5: deterministic final reduction
// ---------------------------------------------------------------------------
__global__ void k_reduce(float* __restrict__ out) {
    __shared__ float sm[256];
    int tid = threadIdx.x;
    float s = 0.0f;
    for (int i = tid; i < NSTEP * MROWS; i += 256) s += g_part[i];
    sm[tid] = s;
    __syncthreads();
    for (int o = 128; o; o >>= 1) {
        if (tid < o) sm[tid] += sm[tid + o];
        __syncthreads();
    }
    if (tid == 0) out[0] = sm[0];
}

// ---------------------------------------------------------------------------
extern "C" void kernel_launch(void* const* d_in, const int* in_sizes, int n_in,
                              void* d_out, int out_size) {
    const float* ctx  = (const float*)d_in[0];
    const float* tgt  = (const float*)d_in[1];
    const float* W    = (const float*)d_in[2];
    const float* bias = (const float*)d_in[3];
    float* out = (float*)d_out;

    uint32_t* abf;  cudaGetSymbolAddress((void**)&abf, g_Abf);
    uint32_t* bbf;  cudaGetSymbolAddress((void**)&bbf, g_Bbf);

    k_norm_targets<<<(BATCH * TLEN) / 8, 256>>>(tgt);
    k_cvt<<<(MROWS * DIM / 2) / 256, 256>>>((const float2*)ctx, abf, MROWS * DIM / 2);
    k_cvt<<<(NCOLS * DIM / 2) / 256, 256>>>((const float2*)W, bbf, NCOLS * DIM / 2);
    k_mma<<<dim3(NCOLS / 128, MROWS / 128), 256>>>();
    k_bias_norm<<<(MROWS * NSTEP) / 8, 256>>>(bias);
    k_loss<<<dim3(MROWS, NSTEP), 256>>>();
    k_reduce<<<1, 256>>>(out);
}

// round 13
// speedup vs baseline: 1.6950x; 1.0452x over previous
#include <cuda_runtime.h>
#include <cuda_bf16.h>
#include <cstdint>

#define BATCH 8
#define TLEN 256
#define DIM 256
#define NSTEP 12
#define NNEG 100
#define MROWS 2048
#define NCOLS 3072

__device__ float g_C[MROWS * NCOLS];                 // raw GEMM output (f32)
__device__ uint32_t g_Cq[MROWS * NSTEP * 128];       // normalized queries, bf16x2
__device__ __nv_bfloat16 g_tn[MROWS * DIM];          // normalized targets (bf16)
__device__ float g_part[NSTEP * MROWS];              // per-sample loss partials
__device__ uint32_t g_Abf[MROWS * DIM / 2];          // ctx in bf16x2, k-major
__device__ uint32_t g_Bbf[NCOLS * DIM / 2];          // W   in bf16x2, k-major

// ---------------------------------------------------------------------------
// warp reductions (butterfly shfl — f32 redux does NOT exist on sm_103a)
// ---------------------------------------------------------------------------
__device__ __forceinline__ float wsum(float v) {
#pragma unroll
    for (int o = 16; o; o >>= 1) v += __shfl_xor_sync(0xffffffffu, v, o);
    return v;
}
__device__ __forceinline__ float wmax(float v) {
#pragma unroll
    for (int o = 16; o; o >>= 1) v = fmaxf(v, __shfl_xor_sync(0xffffffffu, v, o));
    return v;
}

// ---------------------------------------------------------------------------
// Threefry-2x32 (exact JAX rotation/key schedule)
// ---------------------------------------------------------------------------
__device__ __forceinline__ void tf2x32(uint32_t k0, uint32_t k1,
                                       uint32_t x0, uint32_t x1,
                                       uint32_t &o0, uint32_t &o1) {
    uint32_t ks2 = k0 ^ k1 ^ 0x1BD11BDAu;
    x0 += k0; x1 += k1;
#define TFR(r) { x0 += x1; x1 = __funnelshift_l(x1, x1, (r)); x1 ^= x0; }
    TFR(13) TFR(15) TFR(26) TFR(6)   x0 += k1;  x1 += ks2 + 1u;
    TFR(17) TFR(29) TFR(16) TFR(24)  x0 += ks2; x1 += k0 + 2u;
    TFR(13) TFR(15) TFR(26) TFR(6)   x0 += k0;  x1 += k1 + 3u;
    TFR(17) TFR(29) TFR(16) TFR(24)  x0 += k1;  x1 += ks2 + 4u;
    TFR(13) TFR(15) TFR(26) TFR(6)   x0 += ks2; x1 += k0 + 5u;
#undef TFR
    o0 = x0; o1 = x1;
}

__device__ __forceinline__ uint32_t tf_bits32(uint32_t k0, uint32_t k1, uint32_t i) {
    uint32_t a, b;
    tf2x32(k0, k1, 0u, i, a, b);
    return a ^ b;
}

// ---------------------------------------------------------------------------
// bf16x2 helpers
// ---------------------------------------------------------------------------
__device__ __forceinline__ void bfma2(uint32_t &acc, uint32_t a, uint32_t b) {
    asm("fma.rn.bf16x2 %0, %1, %2, %3;" : "=r"(acc) : "r"(a), "r"(b), "r"(acc));
}
__device__ __forceinline__ uint32_t f2_to_bf2(float lo, float hi) {
    __nv_bfloat162 p = __floats2bfloat162_rn(lo, hi);   // .x = lo (low half)
    return *reinterpret_cast<uint32_t*>(&p);
}

// ---------------------------------------------------------------------------
// async copy / ldmatrix / mma primitives
// ---------------------------------------------------------------------------
__device__ __forceinline__ void cpa16(uint32_t dst, const void* src) {
    asm volatile("cp.async.cg.shared.global [%0], [%1], 16;"
                 :: "r"(dst), "l"(src));
}
__device__ __forceinline__ void ldsm4(uint32_t &r0, uint32_t &r1,
                                      uint32_t &r2, uint32_t &r3, uint32_t a) {
    asm volatile("ldmatrix.sync.aligned.m8n8.x4.shared.b16 {%0,%1,%2,%3}, [%4];"
                 : "=r"(r0), "=r"(r1), "=r"(r2), "=r"(r3) : "r"(a));
}
__device__ __forceinline__ void mma_bf16(float* d, const uint32_t* a,
                                         uint32_t b0, uint32_t b1) {
    asm("mma.sync.aligned.m16n8k16.row.col.f32.bf16.bf16.f32 "
        "{%0,%1,%2,%3}, {%4,%5,%6,%7}, {%8,%9}, {%0,%1,%2,%3};"
        : "+f"(d[0]), "+f"(d[1]), "+f"(d[2]), "+f"(d[3])
        : "r"(a[0]), "r"(a[1]), "r"(a[2]), "r"(a[3]), "r"(b0), "r"(b1));
}

// ---------------------------------------------------------------------------
// Kernel 0: fp32 -> bf16x2 conversion (pairs; n = number of float2 pairs)
// ---------------------------------------------------------------------------
__global__ void k_cvt(const float2* __restrict__ src, uint32_t* __restrict__ dst,
                      int n) {
    int i = blockIdx.x * blockDim.x + threadIdx.x;
    if (i < n) {
        float2 v = src[i];
        dst[i] = f2_to_bf2(v.x, v.y);
    }
}

// ---------------------------------------------------------------------------
// Kernel 1: normalize target rows, store bf16
// ---------------------------------------------------------------------------
__global__ void k_norm_targets(const float* __restrict__ tgt) {
    int gw = (blockIdx.x * blockDim.x + threadIdx.x) >> 5;
    int lane = threadIdx.x & 31;
    if (gw >= BATCH * TLEN) return;
    const float4* r = reinterpret_cast<const float4*>(tgt + (size_t)gw * DIM);
    float4 a = r[lane * 2];
    float4 b = r[lane * 2 + 1];
    float ss = a.x*a.x + a.y*a.y + a.z*a.z + a.w*a.w
             + b.x*b.x + b.y*b.y + b.z*b.z + b.w*b.w;
    ss = wsum(ss);
    float inv = 1.0f / fmaxf(sqrtf(ss), 1e-12f);
    uint4 u;
    u.x = f2_to_bf2(a.x * inv, a.y * inv);
    u.y = f2_to_bf2(a.z * inv, a.w * inv);
    u.z = f2_to_bf2(b.x * inv, b.y * inv);
    u.w = f2_to_bf2(b.z * inv, b.w * inv);
    reinterpret_cast<uint4*>(g_tn + (size_t)gw * DIM)[lane] = u;
}

// ---------------------------------------------------------------------------
// Kernel 2: C[2048,3072] = A[2048,256] * B[3072,256]^T via smem-tiled HMMA.
//   Block tile 128x128, 8 warps (warp = 32x64), K chunks of 32, double-
//   buffered cp.async.cg, fragments via ldmatrix.x4. Smem rows padded to
//   80B -> LDSM 8-row address sets hit 8 distinct 16B slots (conflict-free).
// ---------------------------------------------------------------------------
#define KCHUNKS 8
#define ROWB 80                      // padded row stride in bytes (32 bf16 + pad)
#define TILEB (128 * ROWB)           // 10240 B per tile buffer

__global__ __launch_bounds__(256) void k_mma() {
    __shared__ uint8_t sA[2][TILEB];
    __shared__ uint8_t sB[2][TILEB];

    int tid = threadIdx.x;
    int lane = tid & 31, w = tid >> 5;
    int bm = blockIdx.y * 128;       // M block
    int bn = blockIdx.x * 128;       // N block
    int wmo = (w & 3) * 32;          // warp m-offset in tile
    int wno = (w >> 2) * 64;         // warp n-offset in tile

    uint32_t sAu = (uint32_t)__cvta_generic_to_shared(&sA[0][0]);
    uint32_t sBu = (uint32_t)__cvta_generic_to_shared(&sB[0][0]);

    // copy indexing: 2 rows per thread per tile (128 rows x 4 segs of 16B)
    int crow = tid >> 2, cseg = tid & 3;
    const uint32_t* gA = g_Abf + (size_t)(bm + crow) * 128 + cseg * 4;
    const uint32_t* gB = g_Bbf + (size_t)(bn + crow) * 128 + cseg * 4;
    uint32_t dA = sAu + crow * ROWB + cseg * 16;
    uint32_t dB = sBu + crow * ROWB + cseg * 16;

#define COPY_CHUNK(c, buf)                                                    \
    {                                                                         \
        cpa16(dA + (buf) * TILEB, gA + (c) * 16);                             \
        cpa16(dA + (buf) * TILEB + 64 * ROWB, gA + 64 * 128 + (c) * 16);      \
        cpa16(dB + (buf) * TILEB, gB + (c) * 16);                            \
        cpa16(dB + (buf) * TILEB + 64 * ROWB, gB + 64 * 128 + (c) * 16);      \
        asm volatile("cp.async.commit_group;");                               \
    }

    float acc[2][8][4];
#pragma unroll
    for (int i = 0; i < 2; i++)
#pragma unroll
        for (int j = 0; j < 8; j++)
#pragma unroll
            for (int k = 0; k < 4; k++) acc[i][j][k] = 0.0f;

    int gh = (lane >> 3) & 1;        // ldmatrix address group: row half
    int kh = lane >> 4;              // ldmatrix address group: k half
    int lr = lane & 7;               // row within 8
    int qr = lane >> 2, kc = lane & 3;

    COPY_CHUNK(0, 0)

    for (int c = 0; c < KCHUNKS; c++) {
        int buf = c & 1;
        if (c < KCHUNKS - 1) COPY_CHUNK(c + 1, buf ^ 1)
        if (c < KCHUNKS - 1) asm volatile("cp.async.wait_group 1;");
        else                 asm volatile("cp.async.wait_group 0;");
        __syncthreads();

        uint32_t aBase = sAu + buf * TILEB;
        uint32_t bBase = sBu + buf * TILEB;
#pragma unroll
        for (int c16 = 0; c16 < 2; c16++) {
            uint32_t kbyte = c16 * 32 + kh * 16;
            uint32_t a[2][4];
#pragma unroll
            for (int mf = 0; mf < 2; mf++) {
                uint32_t addr = aBase + (wmo + mf * 16 + gh * 8 + lr) * ROWB + kbyte;
                ldsm4(a[mf][0], a[mf][1], a[mf][2], a[mf][3], addr);
            }
#pragma unroll
            for (int nfp = 0; nfp < 4; nfp++) {
                uint32_t b0, b1, b2, b3;
                uint32_t addr = bBase + (wno + nfp * 16 + gh * 8 + lr) * ROWB + kbyte;
                ldsm4(b0, b1, b2, b3, addr);
                mma_bf16(acc[0][nfp * 2],     a[0], b0, b2);
                mma_bf16(acc[0][nfp * 2 + 1], a[0], b1, b3);
                mma_bf16(acc[1][nfp * 2],     a[1], b0, b2);
                mma_bf16(acc[1][nfp * 2 + 1], a[1], b1, b3);
            }
        }
        __syncthreads();
    }
#undef COPY_CHUNK

    // Epilogue: D row r: c0,c1 at (qr, 2kc); c2,c3 at row +8. float2 stores.
#pragma unroll
    for (int mf = 0; mf < 2; mf++) {
#pragma unroll
        for (int nf = 0; nf < 8; nf++) {
            float* d = acc[mf][nf];
            int r = bm + wmo + mf * 16 + qr;
            int cc = bn + wno + nf * 8 + kc * 2;
            *reinterpret_cast<float2*>(g_C + (size_t)r * NCOLS + cc) =
                make_float2(d[0], d[1]);
            *reinterpret_cast<float2*>(g_C + (size_t)(r + 8) * NCOLS + cc) =
                make_float2(d[2], d[3]);
        }
    }
}

// ---------------------------------------------------------------------------
// Kernel 3: add bias + L2-normalize each query row (warp per row), emit
//   bf16x2 directly into g_Cq (exactly the rounding k_loss used to apply).
// ---------------------------------------------------------------------------
__global__ void k_bias_norm(const float* __restrict__ bias) {
    int gw = (blockIdx.x * blockDim.x + threadIdx.x) >> 5;
    int lane = threadIdx.x & 31;
    if (gw >= MROWS * NSTEP) return;
    int m = gw / NSTEP, s = gw % NSTEP;
    const float* row = g_C + (size_t)m * NCOLS + (size_t)s * DIM;
    const float4* b4 = reinterpret_cast<const float4*>(bias + (size_t)s * DIM);
    float4 v0 = reinterpret_cast<const float4*>(row)[lane * 2];
    float4 v1 = reinterpret_cast<const float4*>(row)[lane * 2 + 1];
    float4 c0 = b4[lane * 2];
    float4 c1 = b4[lane * 2 + 1];
    v0.x += c0.x; v0.y += c0.y; v0.z += c0.z; v0.w += c0.w;
    v1.x += c1.x; v1.y += c1.y; v1.z += c1.z; v1.w += c1.w;
    float ss = v0.x*v0.x + v0.y*v0.y + v0.z*v0.z + v0.w*v0.w
             + v1.x*v1.x + v1.y*v1.y + v1.z*v1.z + v1.w*v1.w;
    ss = wsum(ss);
    float inv = 1.0f / fmaxf(sqrtf(ss), 1e-12f);
    uint4 o;
    o.x = f2_to_bf2(v0.x * inv, v0.y * inv);
    o.y = f2_to_bf2(v0.z * inv, v0.w * inv);
    o.z = f2_to_bf2(v1.x * inv, v1.y * inv);
    o.w = f2_to_bf2(v1.z * inv, v1.w * inv);
    uint32_t* qdst = g_Cq + ((size_t)m * NSTEP + s) * 128;
    reinterpret_cast<uint4*>(qdst)[lane] = o;
}

// ---------------------------------------------------------------------------
// Kernel 4: per-(step,b,t) InfoNCE partial loss (warp-per-item, contiguous
//   512B row per warp-load; bf16x2 FMA dot; smem partial reduce).
//   Block-uniform PRNG constants hoisted to thread 0; reduce phase uses
//   LDS.128 (stride-36 rows keep both phases bank-conflict-free).
// ---------------------------------------------------------------------------
__global__ __launch_bounds__(256) void k_loss() {
    int s = blockIdx.y + 1;           // step 1..12
    int T2 = TLEN - s;
    int bt = blockIdx.x;              // 0..2047
    int b = bt >> 8, t = bt & 255;
    int tid = threadIdx.x;
    __shared__ __align__(16) float sp[101 * 36];  // per-lane partials
    __shared__ float logits[101];
    __shared__ int sidx[104];         // row * 32 (uint4 units); 101..103 = pad
    __shared__ uint32_t cst[3];       // k0, k1, mult
    if (t >= T2) {
        if (tid == 0) g_part[(size_t)(s - 1) * MROWS + bt] = 0.0f;
        return;
    }
    uint32_t span = (uint32_t)(BATCH * T2);
    if (tid == 0) {
        uint32_t k0, k1;
        tf2x32(0u, 1234u, 0u, (uint32_t)s, k0, k1);   // fold_in(key(1234), s)
        uint32_t m16 = 65536u % span;
        cst[0] = k0; cst[1] = k1; cst[2] = (m16 * m16) % span;
    }
    __syncthreads();
    if (tid < 104) {
        int row = 0;                  // pad rows -> row 0 (discarded)
        if (tid == 0) {
            row = b * TLEN + t + s;   // positive
        } else if (tid < 101) {
            uint32_t k0 = cst[0], k1 = cst[1], mult = cst[2];
            uint32_t n = span * NNEG;
            uint32_t i = (uint32_t)((b * T2 + t) * NNEG + (tid - 1));
            uint32_t hi = tf_bits32(k0, k1, i);
            uint32_t lo = tf_bits32(k0, k1, n + i);
            uint32_t off = ((hi % span) * mult + (lo % span)) % span;
            uint32_t b2 = off / (uint32_t)T2;
            uint32_t t2 = off - b2 * (uint32_t)T2;
            row = (int)(b2 * TLEN + (uint32_t)s + t2);
        }
        sidx[tid] = row * 32;
    }
    __syncthreads();

    int lane = tid & 31, w = tid >> 5;

    // Query: this lane's 8 contiguous bf16 pairs, pre-rounded by k_bias_norm
    const uint4* qp = reinterpret_cast<const uint4*>(
        g_Cq + ((size_t)bt * NSTEP + (s - 1)) * 128);
    uint4 q = qp[lane];
    uint32_t qh0 = q.x, qh1 = q.y, qh2 = q.z, qh3 = q.w;

    const uint4* tn4 = reinterpret_cast<const uint4*>(g_tn);
#pragma unroll 4
    for (int it = 0; it < 13; it++) {
        int g = it * 8 + w;           // item id 0..103; uniform across warp
        uint4 v = __ldg(tn4 + sidx[g] + lane);
        uint32_t acc = 0;
        bfma2(acc, v.x, qh0);
        bfma2(acc, v.y, qh1);
        bfma2(acc, v.z, qh2);
        bfma2(acc, v.w, qh3);
        // exact unpack of the bf16x2 accumulator halves
        float part = __uint_as_float(acc << 16)
                   + __uint_as_float(acc & 0xffff0000u);
        if (g < 101) sp[g * 36 + lane] = part;   // warp-uniform predicate
    }
    __syncthreads();

    // Reduce 32 lane-partials per item with LDS.128 (thread i -> item i).
    // Banks: lanes 0-7 of a warp cover banks 0-31 exactly (36*4=144B rows).
    if (tid < 101) {
        const float4* r4 = reinterpret_cast<const float4*>(sp + tid * 36);
        float4 a0 = r4[0], a1 = r4[1], a2 = r4[2], a3 = r4[3];
        float4 a4 = r4[4], a5 = r4[5], a6 = r4[6], a7 = r4[7];
        float s0 = (a0.x + a0.y) + (a0.z + a0.w);
        float s1 = (a1.x + a1.y) + (a1.z + a1.w);
        float s2 = (a2.x + a2.y) + (a2.z + a2.w);
        float s3 = (a3.x + a3.y) + (a3.z + a3.w);
        float s4 = (a4.x + a4.y) + (a4.z + a4.w);
        float s5 = (a5.x + a5.y) + (a5.z + a5.w);
        float s6 = (a6.x + a6.y) + (a6.z + a6.w);
        float s7 = (a7.x + a7.y) + (a7.z + a7.w);
        logits[tid] = (((s0 + s1) + (s2 + s3)) + ((s4 + s5) + (s6 + s7))) * 10.0f;
    }
    __syncthreads();

    if (w == 0) {
        float mx = -1e30f;
        for (int i = lane; i < 101; i += 32) mx = fmaxf(mx, logits[i]);
        mx = wmax(mx);
        float sum = 0.0f;
        for (int i = lane; i < 101; i += 32) sum += __expf(logits[i] - mx);
        sum = wsum(sum);
        if (lane == 0) {
            float lse = mx + __logf(sum);
            g_part[(size_t)(s - 1) * MROWS + bt] =
                (lse - logits[0]) / (float)(NSTEP * BATCH * T2);
        }
    }
}

// ---------------------------------------------------------------------------
// Kernel 5: deterministic final reduction
// ---------------------------------------------------------------------------
__global__ void k_reduce(float* __restrict__ out) {
    __shared__ float sm[256];
    int tid = threadIdx.x;
    float s = 0.0f;
    for (int i = tid; i < NSTEP * MROWS; i += 256) s += g_part[i];
    sm[tid] = s;
    __syncthreads();
    for (int o = 128; o; o >>= 1) {
        if (tid < o) sm[tid] += sm[tid + o];
        __syncthreads();
    }
    if (tid == 0) out[0] = sm[0];
}

// ---------------------------------------------------------------------------
extern "C" void kernel_launch(void* const* d_in, const int* in_sizes, int n_in,
                              void* d_out, int out_size) {
    const float* ctx  = (const float*)d_in[0];
    const float* tgt  = (const float*)d_in[1];
    const float* W    = (const float*)d_in[2];
    const float* bias = (const float*)d_in[3];
    float* out = (float*)d_out;

    uint32_t* abf;  cudaGetSymbolAddress((void**)&abf, g_Abf);
    uint32_t* bbf;  cudaGetSymbolAddress((void**)&bbf, g_Bbf);

    k_norm_targets<<<(BATCH * TLEN) / 8, 256>>>(tgt);
    k_cvt<<<(MROWS * DIM / 2) / 256, 256>>>((const float2*)ctx, abf, MROWS * DIM / 2);
    k_cvt<<<(NCOLS * DIM / 2) / 256, 256>>>((const float2*)W, bbf, NCOLS * DIM / 2);
    k_mma<<<dim3(NCOLS / 128, MROWS / 128), 256>>>();
    k_bias_norm<<<(MROWS * NSTEP) / 8, 256>>>(bias);
    k_loss<<<dim3(MROWS, NSTEP), 256>>>();
    k_reduce<<<1, 256>>>(out);
}

// round 14
// speedup vs baseline: 1.8125x; 1.0693x over previous
#include <cuda_runtime.h>
#include <cuda_bf16.h>
#include <cstdint>

#define BATCH 8
#define TLEN 256
#define DIM 256
#define NSTEP 12
#define NNEG 100
#define MROWS 2048
#define NCOLS 3072

__device__ float g_C[MROWS * NCOLS];                 // raw GEMM output (f32)
__device__ uint32_t g_Cq[MROWS * NSTEP * 64];        // normalized queries, s8x4
__device__ uint32_t g_tn8[MROWS * 64];               // normalized targets, s8x4
__device__ float g_part[NSTEP * MROWS];              // per-sample loss partials
__device__ uint32_t g_Abf[MROWS * DIM / 2];          // ctx in bf16x2, k-major
__device__ uint32_t g_Bbf[NCOLS * DIM / 2];          // W   in bf16x2, k-major

// ---------------------------------------------------------------------------
// warp reductions (butterfly shfl — f32 redux does NOT exist on sm_103a)
// ---------------------------------------------------------------------------
__device__ __forceinline__ float wsum(float v) {
#pragma unroll
    for (int o = 16; o; o >>= 1) v += __shfl_xor_sync(0xffffffffu, v, o);
    return v;
}
__device__ __forceinline__ float wmax(float v) {
#pragma unroll
    for (int o = 16; o; o >>= 1) v = fmaxf(v, __shfl_xor_sync(0xffffffffu, v, o));
    return v;
}

// ---------------------------------------------------------------------------
// Threefry-2x32 (exact JAX rotation/key schedule)
// ---------------------------------------------------------------------------
__device__ __forceinline__ void tf2x32(uint32_t k0, uint32_t k1,
                                       uint32_t x0, uint32_t x1,
                                       uint32_t &o0, uint32_t &o1) {
    uint32_t ks2 = k0 ^ k1 ^ 0x1BD11BDAu;
    x0 += k0; x1 += k1;
#define TFR(r) { x0 += x1; x1 = __funnelshift_l(x1, x1, (r)); x1 ^= x0; }
    TFR(13) TFR(15) TFR(26) TFR(6)   x0 += k1;  x1 += ks2 + 1u;
    TFR(17) TFR(29) TFR(16) TFR(24)  x0 += ks2; x1 += k0 + 2u;
    TFR(13) TFR(15) TFR(26) TFR(6)   x0 += k0;  x1 += k1 + 3u;
    TFR(17) TFR(29) TFR(16) TFR(24)  x0 += k1;  x1 += ks2 + 4u;
    TFR(13) TFR(15) TFR(26) TFR(6)   x0 += ks2; x1 += k0 + 5u;
#undef TFR
    o0 = x0; o1 = x1;
}

__device__ __forceinline__ uint32_t tf_bits32(uint32_t k0, uint32_t k1, uint32_t i) {
    uint32_t a, b;
    tf2x32(k0, k1, 0u, i, a, b);
    return a ^ b;
}

// ---------------------------------------------------------------------------
// bf16x2 / int8 helpers
// ---------------------------------------------------------------------------
__device__ __forceinline__ uint32_t f2_to_bf2(float lo, float hi) {
    __nv_bfloat162 p = __floats2bfloat162_rn(lo, hi);   // .x = lo (low half)
    return *reinterpret_cast<uint32_t*>(&p);
}
// pack 4 floats (already scaled to [-127,127]) as s8x4
__device__ __forceinline__ uint32_t pack_s8x4(float a, float b, float c, float d) {
    int ia = __float2int_rn(a), ib = __float2int_rn(b);
    int ic = __float2int_rn(c), id = __float2int_rn(d);
    return (uint32_t)(ia & 0xff) | ((uint32_t)(ib & 0xff) << 8) |
           ((uint32_t)(ic & 0xff) << 16) | ((uint32_t)(id & 0xff) << 24);
}

// ---------------------------------------------------------------------------
// async copy / ldmatrix / mma primitives
// ---------------------------------------------------------------------------
__device__ __forceinline__ void cpa16(uint32_t dst, const void* src) {
    asm volatile("cp.async.cg.shared.global [%0], [%1], 16;"
                 :: "r"(dst), "l"(src));
}
__device__ __forceinline__ void ldsm4(uint32_t &r0, uint32_t &r1,
                                      uint32_t &r2, uint32_t &r3, uint32_t a) {
    asm volatile("ldmatrix.sync.aligned.m8n8.x4.shared.b16 {%0,%1,%2,%3}, [%4];"
                 : "=r"(r0), "=r"(r1), "=r"(r2), "=r"(r3) : "r"(a));
}
__device__ __forceinline__ void mma_bf16(float* d, const uint32_t* a,
                                         uint32_t b0, uint32_t b1) {
    asm("mma.sync.aligned.m16n8k16.row.col.f32.bf16.bf16.f32 "
        "{%0,%1,%2,%3}, {%4,%5,%6,%7}, {%8,%9}, {%0,%1,%2,%3};"
        : "+f"(d[0]), "+f"(d[1]), "+f"(d[2]), "+f"(d[3])
        : "r"(a[0]), "r"(a[1]), "r"(a[2]), "r"(a[3]), "r"(b0), "r"(b1));
}

// ---------------------------------------------------------------------------
// Kernel 0: fp32 -> bf16x2 conversion (pairs; n = number of float2 pairs)
// ---------------------------------------------------------------------------
__global__ void k_cvt(const float2* __restrict__ src, uint32_t* __restrict__ dst,
                      int n) {
    int i = blockIdx.x * blockDim.x + threadIdx.x;
    if (i < n) {
        float2 v = src[i];
        dst[i] = f2_to_bf2(v.x, v.y);
    }
}

// ---------------------------------------------------------------------------
// Kernel 1: normalize target rows, store s8 (uniform scale 127)
// ---------------------------------------------------------------------------
__global__ void k_norm_targets(const float* __restrict__ tgt) {
    int gw = (blockIdx.x * blockDim.x + threadIdx.x) >> 5;
    int lane = threadIdx.x & 31;
    if (gw >= BATCH * TLEN) return;
    const float4* r = reinterpret_cast<const float4*>(tgt + (size_t)gw * DIM);
    float4 a = r[lane * 2];
    float4 b = r[lane * 2 + 1];
    float ss = a.x*a.x + a.y*a.y + a.z*a.z + a.w*a.w
             + b.x*b.x + b.y*b.y + b.z*b.z + b.w*b.w;
    ss = wsum(ss);
    float q = 127.0f / fmaxf(sqrtf(ss), 1e-12f);
    uint2 u;
    u.x = pack_s8x4(a.x * q, a.y * q, a.z * q, a.w * q);
    u.y = pack_s8x4(b.x * q, b.y * q, b.z * q, b.w * q);
    reinterpret_cast<uint2*>(g_tn8 + (size_t)gw * 64)[lane] = u;
}

// ---------------------------------------------------------------------------
// Kernel 2: C[2048,3072] = A[2048,256] * B[3072,256]^T via smem-tiled HMMA.
//   Block tile 128x128, 8 warps (warp = 32x64), K chunks of 32, double-
//   buffered cp.async.cg, fragments via ldmatrix.x4. Smem rows padded to
//   80B -> LDSM 8-row address sets hit 8 distinct 16B slots (conflict-free).
//   min-blocks 3 to lift occupancy (latency-bound mainloop).
// ---------------------------------------------------------------------------
#define KCHUNKS 8
#define ROWB 80                      // padded row stride in bytes (32 bf16 + pad)
#define TILEB (128 * ROWB)           // 10240 B per tile buffer

__global__ __launch_bounds__(256, 3) void k_mma() {
    __shared__ uint8_t sA[2][TILEB];
    __shared__ uint8_t sB[2][TILEB];

    int tid = threadIdx.x;
    int lane = tid & 31, w = tid >> 5;
    int bm = blockIdx.y * 128;       // M block
    int bn = blockIdx.x * 128;       // N block
    int wmo = (w & 3) * 32;          // warp m-offset in tile
    int wno = (w >> 2) * 64;         // warp n-offset in tile

    uint32_t sAu = (uint32_t)__cvta_generic_to_shared(&sA[0][0]);
    uint32_t sBu = (uint32_t)__cvta_generic_to_shared(&sB[0][0]);

    // copy indexing: 2 rows per thread per tile (128 rows x 4 segs of 16B)
    int crow = tid >> 2, cseg = tid & 3;
    const uint32_t* gA = g_Abf + (size_t)(bm + crow) * 128 + cseg * 4;
    const uint32_t* gB = g_Bbf + (size_t)(bn + crow) * 128 + cseg * 4;
    uint32_t dA = sAu + crow * ROWB + cseg * 16;
    uint32_t dB = sBu + crow * ROWB + cseg * 16;

#define COPY_CHUNK(c, buf)                                                    \
    {                                                                         \
        cpa16(dA + (buf) * TILEB, gA + (c) * 16);                             \
        cpa16(dA + (buf) * TILEB + 64 * ROWB, gA + 64 * 128 + (c) * 16);      \
        cpa16(dB + (buf) * TILEB, gB + (c) * 16);                            \
        cpa16(dB + (buf) * TILEB + 64 * ROWB, gB + 64 * 128 + (c) * 16);      \
        asm volatile("cp.async.commit_group;");                               \
    }

    float acc[2][8][4];
#pragma unroll
    for (int i = 0; i < 2; i++)
#pragma unroll
        for (int j = 0; j < 8; j++)
#pragma unroll
            for (int k = 0; k < 4; k++) acc[i][j][k] = 0.0f;

    int gh = (lane >> 3) & 1;        // ldmatrix address group: row half
    int kh = lane >> 4;              // ldmatrix address group: k half
    int lr = lane & 7;               // row within 8
    int qr = lane >> 2, kc = lane & 3;

    COPY_CHUNK(0, 0)

    for (int c = 0; c < KCHUNKS; c++) {
        int buf = c & 1;
        if (c < KCHUNKS - 1) COPY_CHUNK(c + 1, buf ^ 1)
        if (c < KCHUNKS - 1) asm volatile("cp.async.wait_group 1;");
        else                 asm volatile("cp.async.wait_group 0;");
        __syncthreads();

        uint32_t aBase = sAu + buf * TILEB;
        uint32_t bBase = sBu + buf * TILEB;
#pragma unroll
        for (int c16 = 0; c16 < 2; c16++) {
            uint32_t kbyte = c16 * 32 + kh * 16;
            uint32_t a[2][4];
#pragma unroll
            for (int mf = 0; mf < 2; mf++) {
                uint32_t addr = aBase + (wmo + mf * 16 + gh * 8 + lr) * ROWB + kbyte;
                ldsm4(a[mf][0], a[mf][1], a[mf][2], a[mf][3], addr);
            }
#pragma unroll
            for (int nfp = 0; nfp < 4; nfp++) {
                uint32_t b0, b1, b2, b3;
                uint32_t addr = bBase + (wno + nfp * 16 + gh * 8 + lr) * ROWB + kbyte;
                ldsm4(b0, b1, b2, b3, addr);
                mma_bf16(acc[0][nfp * 2],     a[0], b0, b2);
                mma_bf16(acc[0][nfp * 2 + 1], a[0], b1, b3);
                mma_bf16(acc[1][nfp * 2],     a[1], b0, b2);
                mma_bf16(acc[1][nfp * 2 + 1], a[1], b1, b3);
            }
        }
        __syncthreads();
    }
#undef COPY_CHUNK

    // Epilogue: D row r: c0,c1 at (qr, 2kc); c2,c3 at row +8. float2 stores.
#pragma unroll
    for (int mf = 0; mf < 2; mf++) {
#pragma unroll
        for (int nf = 0; nf < 8; nf++) {
            float* d = acc[mf][nf];
            int r = bm + wmo + mf * 16 + qr;
            int cc = bn + wno + nf * 8 + kc * 2;
            *reinterpret_cast<float2*>(g_C + (size_t)r * NCOLS + cc) =
                make_float2(d[0], d[1]);
            *reinterpret_cast<float2*>(g_C + (size_t)(r + 8) * NCOLS + cc) =
                make_float2(d[2], d[3]);
        }
    }
}

// ---------------------------------------------------------------------------
// Kernel 3: add bias + L2-normalize each query row (warp per row), emit
//   s8x4 (uniform scale 127) into g_Cq.
// ---------------------------------------------------------------------------
__global__ void k_bias_norm(const float* __restrict__ bias) {
    int gw = (blockIdx.x * blockDim.x + threadIdx.x) >> 5;
    int lane = threadIdx.x & 31;
    if (gw >= MROWS * NSTEP) return;
    int m = gw / NSTEP, s = gw % NSTEP;
    const float* row = g_C + (size_t)m * NCOLS + (size_t)s * DIM;
    const float4* b4 = reinterpret_cast<const float4*>(bias + (size_t)s * DIM);
    float4 v0 = reinterpret_cast<const float4*>(row)[lane * 2];
    float4 v1 = reinterpret_cast<const float4*>(row)[lane * 2 + 1];
    float4 c0 = b4[lane * 2];
    float4 c1 = b4[lane * 2 + 1];
    v0.x += c0.x; v0.y += c0.y; v0.z += c0.z; v0.w += c0.w;
    v1.x += c1.x; v1.y += c1.y; v1.z += c1.z; v1.w += c1.w;
    float ss = v0.x*v0.x + v0.y*v0.y + v0.z*v0.z + v0.w*v0.w
             + v1.x*v1.x + v1.y*v1.y + v1.z*v1.z + v1.w*v1.w;
    ss = wsum(ss);
    float q = 127.0f / fmaxf(sqrtf(ss), 1e-12f);
    uint2 o;
    o.x = pack_s8x4(v0.x * q, v0.y * q, v0.z * q, v0.w * q);
    o.y = pack_s8x4(v1.x * q, v1.y * q, v1.z * q, v1.w * q);
    uint32_t* qdst = g_Cq + ((size_t)m * NSTEP + s) * 64;
    reinterpret_cast<uint2*>(qdst)[lane] = o;
}

// ---------------------------------------------------------------------------
// Kernel 4: per-(step,b,t) InfoNCE partial loss. Warp-per-item over s8 rows
//   (256B/row: warp LDG.64 = 2 wavefronts); dot = 2 DP4A per lane, int32
//   partials are EXACT; smem int reduce via LDS.128; logits scaled once by
//   10/127^2. PRNG constants hoisted; all warp ops fully converged.
// ---------------------------------------------------------------------------
__global__ __launch_bounds__(256) void k_loss() {
    int s = blockIdx.y + 1;           // step 1..12
    int T2 = TLEN - s;
    int bt = blockIdx.x;              // 0..2047
    int b = bt >> 8, t = bt & 255;
    int tid = threadIdx.x;
    __shared__ __align__(16) int sp[101 * 36];  // per-lane int partials
    __shared__ float logits[101];
    __shared__ int sidx[104];         // row * 32 (uint2 units); 101..103 = pad
    __shared__ uint32_t cst[3];       // k0, k1, mult
    if (t >= T2) {
        if (tid == 0) g_part[(size_t)(s - 1) * MROWS + bt] = 0.0f;
        return;
    }
    uint32_t span = (uint32_t)(BATCH * T2);
    if (tid == 0) {
        uint32_t k0, k1;
        tf2x32(0u, 1234u, 0u, (uint32_t)s, k0, k1);   // fold_in(key(1234), s)
        uint32_t m16 = 65536u % span;
        cst[0] = k0; cst[1] = k1; cst[2] = (m16 * m16) % span;
    }
    __syncthreads();
    if (tid < 104) {
        int row = 0;                  // pad rows -> row 0 (discarded)
        if (tid == 0) {
            row = b * TLEN + t + s;   // positive
        } else if (tid < 101) {
            uint32_t k0 = cst[0], k1 = cst[1], mult = cst[2];
            uint32_t n = span * NNEG;
            uint32_t i = (uint32_t)((b * T2 + t) * NNEG + (tid - 1));
            uint32_t hi = tf_bits32(k0, k1, i);
            uint32_t lo = tf_bits32(k0, k1, n + i);
            uint32_t off = ((hi % span) * mult + (lo % span)) % span;
            uint32_t b2 = off / (uint32_t)T2;
            uint32_t t2 = off - b2 * (uint32_t)T2;
            row = (int)(b2 * TLEN + (uint32_t)s + t2);
        }
        sidx[tid] = row * 32;
    }
    __syncthreads();

    int lane = tid & 31, w = tid >> 5;

    // Query: this lane's 8 contiguous s8 elements (one uint2)
    const uint2* qp = reinterpret_cast<const uint2*>(
        g_Cq + ((size_t)bt * NSTEP + (s - 1)) * 64);
    uint2 q = qp[lane];

    const uint2* tn2 = reinterpret_cast<const uint2*>(g_tn8);
#pragma unroll 4
    for (int it = 0; it < 13; it++) {
        int g = it * 8 + w;           // item id 0..103; uniform across warp
        uint2 v = __ldg(tn2 + sidx[g] + lane);
        int d = __dp4a((int)v.x, (int)q.x, __dp4a((int)v.y, (int)q.y, 0));
        if (g < 101) sp[g * 36 + lane] = d;   // warp-uniform predicate
    }
    __syncthreads();

    // Reduce 32 int partials per item with LDS.128 (thread i -> item i).
    // 144B rows: 8 consecutive threads' int4 loads cover all 32 banks.
    if (tid < 101) {
        const int4* r4 = reinterpret_cast<const int4*>(sp + tid * 36);
        int4 a0 = r4[0], a1 = r4[1], a2 = r4[2], a3 = r4[3];
        int4 a4 = r4[4], a5 = r4[5], a6 = r4[6], a7 = r4[7];
        int s0 = (a0.x + a0.y) + (a0.z + a0.w);
        int s1 = (a1.x + a1.y) + (a1.z + a1.w);
        int s2 = (a2.x + a2.y) + (a2.z + a2.w);
        int s3 = (a3.x + a3.y) + (a3.z + a3.w);
        int s4 = (a4.x + a4.y) + (a4.z + a4.w);
        int s5 = (a5.x + a5.y) + (a5.z + a5.w);
        int s6 = (a6.x + a6.y) + (a6.z + a6.w);
        int s7 = (a7.x + a7.y) + (a7.z + a7.w);
        int tot = (((s0 + s1) + (s2 + s3)) + ((s4 + s5) + (s6 + s7)));
        logits[tid] = (float)tot * (10.0f / 16129.0f);   // /TEMP / 127^2
    }
    __syncthreads();

    if (w == 0) {
        float mx = -1e30f;
        for (int i = lane; i < 101; i += 32) mx = fmaxf(mx, logits[i]);
        mx = wmax(mx);
        float sum = 0.0f;
        for (int i = lane; i < 101; i += 32) sum += __expf(logits[i] - mx);
        sum = wsum(sum);
        if (lane == 0) {
            float lse = mx + __logf(sum);
            g_part[(size_t)(s - 1) * MROWS + bt] =
                (lse - logits[0]) / (float)(NSTEP * BATCH * T2);
        }
    }
}

// ---------------------------------------------------------------------------
// Kernel 5: deterministic final reduction
// ---------------------------------------------------------------------------
__global__ void k_reduce(float* __restrict__ out) {
    __shared__ float sm[256];
    int tid = threadIdx.x;
    float s = 0.0f;
    for (int i = tid; i < NSTEP * MROWS; i += 256) s += g_part[i];
    sm[tid] = s;
    __syncthreads();
    for (int o = 128; o; o >>= 1) {
        if (tid < o) sm[tid] += sm[tid + o];
        __syncthreads();
    }
    if (tid == 0) out[0] = sm[0];
}

// ---------------------------------------------------------------------------
extern "C" void kernel_launch(void* const* d_in, const int* in_sizes, int n_in,
                              void* d_out, int out_size) {
    const float* ctx  = (const float*)d_in[0];
    const float* tgt  = (const float*)d_in[1];
    const float* W    = (const float*)d_in[2];
    const float* bias = (const float*)d_in[3];
    float* out = (float*)d_out;

    uint32_t* abf;  cudaGetSymbolAddress((void**)&abf, g_Abf);
    uint32_t* bbf;  cudaGetSymbolAddress((void**)&bbf, g_Bbf);

    k_norm_targets<<<(BATCH * TLEN) / 8, 256>>>(tgt);
    k_cvt<<<(MROWS * DIM / 2) / 256, 256>>>((const float2*)ctx, abf, MROWS * DIM / 2);
    k_cvt<<<(NCOLS * DIM / 2) / 256, 256>>>((const float2*)W, bbf, NCOLS * DIM / 2);
    k_mma<<<dim3(NCOLS / 128, MROWS / 128), 256>>>();
    k_bias_norm<<<(MROWS * NSTEP) / 8, 256>>>(bias);
    k_loss<<<dim3(MROWS, NSTEP), 256>>>();
    k_reduce<<<1, 256>>>(out);
}

// round 15
// speedup vs baseline: 2.0487x; 1.1304x over previous
#include <cuda_runtime.h>
#include <cuda_bf16.h>
#include <cstdint>

#define BATCH 8
#define TLEN 256
#define DIM 256
#define NSTEP 12
#define NNEG 100
#define MROWS 2048
#define NCOLS 3072

__device__ float g_C[MROWS * NCOLS];                 // raw GEMM output (f32)
__device__ uint32_t g_Cq[MROWS * NSTEP * 64];        // normalized queries, s8x4
__device__ uint32_t g_tn8[MROWS * 64];               // normalized targets, s8x4
__device__ float g_part[NSTEP * MROWS];              // per-sample loss partials
__device__ uint32_t g_Abf[MROWS * DIM / 2];          // ctx in bf16x2, k-major
__device__ uint32_t g_Bbf[NCOLS * DIM / 2];          // W   in bf16x2, k-major

// ---------------------------------------------------------------------------
// warp reductions (butterfly shfl — f32 redux does NOT exist on sm_103a)
// ---------------------------------------------------------------------------
__device__ __forceinline__ float wsum(float v) {
#pragma unroll
    for (int o = 16; o; o >>= 1) v += __shfl_xor_sync(0xffffffffu, v, o);
    return v;
}
__device__ __forceinline__ float wmax(float v) {
#pragma unroll
    for (int o = 16; o; o >>= 1) v = fmaxf(v, __shfl_xor_sync(0xffffffffu, v, o));
    return v;
}

// ---------------------------------------------------------------------------
// Threefry-2x32 (exact JAX rotation/key schedule)
// ---------------------------------------------------------------------------
__device__ __forceinline__ void tf2x32(uint32_t k0, uint32_t k1,
                                       uint32_t x0, uint32_t x1,
                                       uint32_t &o0, uint32_t &o1) {
    uint32_t ks2 = k0 ^ k1 ^ 0x1BD11BDAu;
    x0 += k0; x1 += k1;
#define TFR(r) { x0 += x1; x1 = __funnelshift_l(x1, x1, (r)); x1 ^= x0; }
    TFR(13) TFR(15) TFR(26) TFR(6)   x0 += k1;  x1 += ks2 + 1u;
    TFR(17) TFR(29) TFR(16) TFR(24)  x0 += ks2; x1 += k0 + 2u;
    TFR(13) TFR(15) TFR(26) TFR(6)   x0 += k0;  x1 += k1 + 3u;
    TFR(17) TFR(29) TFR(16) TFR(24)  x0 += k1;  x1 += ks2 + 4u;
    TFR(13) TFR(15) TFR(26) TFR(6)   x0 += ks2; x1 += k0 + 5u;
#undef TFR
    o0 = x0; o1 = x1;
}

__device__ __forceinline__ uint32_t tf_bits32(uint32_t k0, uint32_t k1, uint32_t i) {
    uint32_t a, b;
    tf2x32(k0, k1, 0u, i, a, b);
    return a ^ b;
}

// ---------------------------------------------------------------------------
// bf16x2 / int8 helpers
// ---------------------------------------------------------------------------
__device__ __forceinline__ uint32_t f2_to_bf2(float lo, float hi) {
    __nv_bfloat162 p = __floats2bfloat162_rn(lo, hi);   // .x = lo (low half)
    return *reinterpret_cast<uint32_t*>(&p);
}
// pack 4 floats (already scaled to [-127,127]) as s8x4
__device__ __forceinline__ uint32_t pack_s8x4(float a, float b, float c, float d) {
    int ia = __float2int_rn(a), ib = __float2int_rn(b);
    int ic = __float2int_rn(c), id = __float2int_rn(d);
    return (uint32_t)(ia & 0xff) | ((uint32_t)(ib & 0xff) << 8) |
           ((uint32_t)(ic & 0xff) << 16) | ((uint32_t)(id & 0xff) << 24);
}

// ---------------------------------------------------------------------------
// async copy / ldmatrix / mma primitives
// ---------------------------------------------------------------------------
__device__ __forceinline__ void cpa16(uint32_t dst, const void* src) {
    asm volatile("cp.async.cg.shared.global [%0], [%1], 16;"
                 :: "r"(dst), "l"(src));
}
__device__ __forceinline__ void ldsm4(uint32_t &r0, uint32_t &r1,
                                      uint32_t &r2, uint32_t &r3, uint32_t a) {
    asm volatile("ldmatrix.sync.aligned.m8n8.x4.shared.b16 {%0,%1,%2,%3}, [%4];"
                 : "=r"(r0), "=r"(r1), "=r"(r2), "=r"(r3) : "r"(a));
}
__device__ __forceinline__ void mma_bf16(float* d, const uint32_t* a,
                                         uint32_t b0, uint32_t b1) {
    asm("mma.sync.aligned.m16n8k16.row.col.f32.bf16.bf16.f32 "
        "{%0,%1,%2,%3}, {%4,%5,%6,%7}, {%8,%9}, {%0,%1,%2,%3};"
        : "+f"(d[0]), "+f"(d[1]), "+f"(d[2]), "+f"(d[3])
        : "r"(a[0]), "r"(a[1]), "r"(a[2]), "r"(a[3]), "r"(b0), "r"(b1));
}

// ---------------------------------------------------------------------------
// Kernel 0: fp32 -> bf16x2 conversion (pairs; n = number of float2 pairs)
// ---------------------------------------------------------------------------
__global__ void k_cvt(const float2* __restrict__ src, uint32_t* __restrict__ dst,
                      int n) {
    int i = blockIdx.x * blockDim.x + threadIdx.x;
    if (i < n) {
        float2 v = src[i];
        dst[i] = f2_to_bf2(v.x, v.y);
    }
}

// ---------------------------------------------------------------------------
// Kernel 1: normalize target rows, store s8 (uniform scale 127)
// ---------------------------------------------------------------------------
__global__ void k_norm_targets(const float* __restrict__ tgt) {
    int gw = (blockIdx.x * blockDim.x + threadIdx.x) >> 5;
    int lane = threadIdx.x & 31;
    if (gw >= BATCH * TLEN) return;
    const float4* r = reinterpret_cast<const float4*>(tgt + (size_t)gw * DIM);
    float4 a = r[lane * 2];
    float4 b = r[lane * 2 + 1];
    float ss = a.x*a.x + a.y*a.y + a.z*a.z + a.w*a.w
             + b.x*b.x + b.y*b.y + b.z*b.z + b.w*b.w;
    ss = wsum(ss);
    float q = 127.0f / fmaxf(sqrtf(ss), 1e-12f);
    uint2 u;
    u.x = pack_s8x4(a.x * q, a.y * q, a.z * q, a.w * q);
    u.y = pack_s8x4(b.x * q, b.y * q, b.z * q, b.w * q);
    reinterpret_cast<uint2*>(g_tn8 + (size_t)gw * 64)[lane] = u;
}

// ---------------------------------------------------------------------------
// Kernel 2: C[2048,3072] = A[2048,256] * B[3072,256]^T via smem-tiled HMMA.
//   Block tile 128x128, 8 warps (warp = 32x64), K chunks of 32, double-
//   buffered cp.async.cg, fragments via ldmatrix.x4. Smem rows padded to
//   80B -> LDSM 8-row address sets hit 8 distinct 16B slots (conflict-free).
//   (Plain launch_bounds(256): the min-blocks=3 variant spilled and LOST.)
// ---------------------------------------------------------------------------
#define KCHUNKS 8
#define ROWB 80                      // padded row stride in bytes (32 bf16 + pad)
#define TILEB (128 * ROWB)           // 10240 B per tile buffer

__global__ __launch_bounds__(256) void k_mma() {
    __shared__ uint8_t sA[2][TILEB];
    __shared__ uint8_t sB[2][TILEB];

    int tid = threadIdx.x;
    int lane = tid & 31, w = tid >> 5;
    int bm = blockIdx.y * 128;       // M block
    int bn = blockIdx.x * 128;       // N block
    int wmo = (w & 3) * 32;          // warp m-offset in tile
    int wno = (w >> 2) * 64;         // warp n-offset in tile

    uint32_t sAu = (uint32_t)__cvta_generic_to_shared(&sA[0][0]);
    uint32_t sBu = (uint32_t)__cvta_generic_to_shared(&sB[0][0]);

    // copy indexing: 2 rows per thread per tile (128 rows x 4 segs of 16B)
    int crow = tid >> 2, cseg = tid & 3;
    const uint32_t* gA = g_Abf + (size_t)(bm + crow) * 128 + cseg * 4;
    const uint32_t* gB = g_Bbf + (size_t)(bn + crow) * 128 + cseg * 4;
    uint32_t dA = sAu + crow * ROWB + cseg * 16;
    uint32_t dB = sBu + crow * ROWB + cseg * 16;

#define COPY_CHUNK(c, buf)                                                    \
    {                                                                         \
        cpa16(dA + (buf) * TILEB, gA + (c) * 16);                             \
        cpa16(dA + (buf) * TILEB + 64 * ROWB, gA + 64 * 128 + (c) * 16);      \
        cpa16(dB + (buf) * TILEB, gB + (c) * 16);                            \
        cpa16(dB + (buf) * TILEB + 64 * ROWB, gB + 64 * 128 + (c) * 16);      \
        asm volatile("cp.async.commit_group;");                               \
    }

    float acc[2][8][4];
#pragma unroll
    for (int i = 0; i < 2; i++)
#pragma unroll
        for (int j = 0; j < 8; j++)
#pragma unroll
            for (int k = 0; k < 4; k++) acc[i][j][k] = 0.0f;

    int gh = (lane >> 3) & 1;        // ldmatrix address group: row half
    int kh = lane >> 4;              // ldmatrix address group: k half
    int lr = lane & 7;               // row within 8
    int qr = lane >> 2, kc = lane & 3;

    COPY_CHUNK(0, 0)

    for (int c = 0; c < KCHUNKS; c++) {
        int buf = c & 1;
        if (c < KCHUNKS - 1) COPY_CHUNK(c + 1, buf ^ 1)
        if (c < KCHUNKS - 1) asm volatile("cp.async.wait_group 1;");
        else                 asm volatile("cp.async.wait_group 0;");
        __syncthreads();

        uint32_t aBase = sAu + buf * TILEB;
        uint32_t bBase = sBu + buf * TILEB;
#pragma unroll
        for (int c16 = 0; c16 < 2; c16++) {
            uint32_t kbyte = c16 * 32 + kh * 16;
            uint32_t a[2][4];
#pragma unroll
            for (int mf = 0; mf < 2; mf++) {
                uint32_t addr = aBase + (wmo + mf * 16 + gh * 8 + lr) * ROWB + kbyte;
                ldsm4(a[mf][0], a[mf][1], a[mf][2], a[mf][3], addr);
            }
#pragma unroll
            for (int nfp = 0; nfp < 4; nfp++) {
                uint32_t b0, b1, b2, b3;
                uint32_t addr = bBase + (wno + nfp * 16 + gh * 8 + lr) * ROWB + kbyte;
                ldsm4(b0, b1, b2, b3, addr);
                mma_bf16(acc[0][nfp * 2],     a[0], b0, b2);
                mma_bf16(acc[0][nfp * 2 + 1], a[0], b1, b3);
                mma_bf16(acc[1][nfp * 2],     a[1], b0, b2);
                mma_bf16(acc[1][nfp * 2 + 1], a[1], b1, b3);
            }
        }
        __syncthreads();
    }
#undef COPY_CHUNK

    // Epilogue: D row r: c0,c1 at (qr, 2kc); c2,c3 at row +8. float2 stores.
#pragma unroll
    for (int mf = 0; mf < 2; mf++) {
#pragma unroll
        for (int nf = 0; nf < 8; nf++) {
            float* d = acc[mf][nf];
            int r = bm + wmo + mf * 16 + qr;
            int cc = bn + wno + nf * 8 + kc * 2;
            *reinterpret_cast<float2*>(g_C + (size_t)r * NCOLS + cc) =
                make_float2(d[0], d[1]);
            *reinterpret_cast<float2*>(g_C + (size_t)(r + 8) * NCOLS + cc) =
                make_float2(d[2], d[3]);
        }
    }
}

// ---------------------------------------------------------------------------
// Kernel 3: add bias + L2-normalize each query row (warp per row), emit
//   s8x4 (uniform scale 127) into g_Cq.
// ---------------------------------------------------------------------------
__global__ void k_bias_norm(const float* __restrict__ bias) {
    int gw = (blockIdx.x * blockDim.x + threadIdx.x) >> 5;
    int lane = threadIdx.x & 31;
    if (gw >= MROWS * NSTEP) return;
    int m = gw / NSTEP, s = gw % NSTEP;
    const float* row = g_C + (size_t)m * NCOLS + (size_t)s * DIM;
    const float4* b4 = reinterpret_cast<const float4*>(bias + (size_t)s * DIM);
    float4 v0 = reinterpret_cast<const float4*>(row)[lane * 2];
    float4 v1 = reinterpret_cast<const float4*>(row)[lane * 2 + 1];
    float4 c0 = b4[lane * 2];
    float4 c1 = b4[lane * 2 + 1];
    v0.x += c0.x; v0.y += c0.y; v0.z += c0.z; v0.w += c0.w;
    v1.x += c1.x; v1.y += c1.y; v1.z += c1.z; v1.w += c1.w;
    float ss = v0.x*v0.x + v0.y*v0.y + v0.z*v0.z + v0.w*v0.w
             + v1.x*v1.x + v1.y*v1.y + v1.z*v1.z + v1.w*v1.w;
    ss = wsum(ss);
    float q = 127.0f / fmaxf(sqrtf(ss), 1e-12f);
    uint2 o;
    o.x = pack_s8x4(v0.x * q, v0.y * q, v0.z * q, v0.w * q);
    o.y = pack_s8x4(v1.x * q, v1.y * q, v1.z * q, v1.w * q);
    uint32_t* qdst = g_Cq + ((size_t)m * NSTEP + s) * 64;
    reinterpret_cast<uint2*>(qdst)[lane] = o;
}

// ---------------------------------------------------------------------------
// Kernel 4: per-(step,b,t) InfoNCE partial loss. Warp-per-item over s8 rows
//   (256B/row: warp LDG.64 = 2 wavefronts); dot = 2 DP4A per lane, int32
//   partials EXACT; smem int reduce via LDS.128. Mainloop FULLY unrolled so
//   all 13 sidx LDS + 13 LDG.64 issue back-to-back (MLP ~13 hides L2 lat).
// ---------------------------------------------------------------------------
__global__ __launch_bounds__(256) void k_loss() {
    int s = blockIdx.y + 1;           // step 1..12
    int T2 = TLEN - s;
    int bt = blockIdx.x;              // 0..2047
    int b = bt >> 8, t = bt & 255;
    int tid = threadIdx.x;
    __shared__ __align__(16) int sp[101 * 36];  // per-lane int partials
    __shared__ float logits[101];
    __shared__ int sidx[104];         // row * 32 (uint2 units); 101..103 = pad
    __shared__ uint32_t cst[3];       // k0, k1, mult
    if (t >= T2) {
        if (tid == 0) g_part[(size_t)(s - 1) * MROWS + bt] = 0.0f;
        return;
    }
    uint32_t span = (uint32_t)(BATCH * T2);
    if (tid == 0) {
        uint32_t k0, k1;
        tf2x32(0u, 1234u, 0u, (uint32_t)s, k0, k1);   // fold_in(key(1234), s)
        uint32_t m16 = 65536u % span;
        cst[0] = k0; cst[1] = k1; cst[2] = (m16 * m16) % span;
    }
    __syncthreads();
    if (tid < 104) {
        int row = 0;                  // pad rows -> row 0 (discarded)
        if (tid == 0) {
            row = b * TLEN + t + s;   // positive
        } else if (tid < 101) {
            uint32_t k0 = cst[0], k1 = cst[1], mult = cst[2];
            uint32_t n = span * NNEG;
            uint32_t i = (uint32_t)((b * T2 + t) * NNEG + (tid - 1));
            uint32_t hi = tf_bits32(k0, k1, i);
            uint32_t lo = tf_bits32(k0, k1, n + i);
            uint32_t off = ((hi % span) * mult + (lo % span)) % span;
            uint32_t b2 = off / (uint32_t)T2;
            uint32_t t2 = off - b2 * (uint32_t)T2;
            row = (int)(b2 * TLEN + (uint32_t)s + t2);
        }
        sidx[tid] = row * 32;
    }
    __syncthreads();

    int lane = tid & 31, w = tid >> 5;

    // Query: this lane's 8 contiguous s8 elements (one uint2)
    const uint2* qp = reinterpret_cast<const uint2*>(
        g_Cq + ((size_t)bt * NSTEP + (s - 1)) * 64);
    uint2 q = qp[lane];

    const uint2* tn2 = reinterpret_cast<const uint2*>(g_tn8);
#pragma unroll
    for (int it = 0; it < 13; it++) {
        int g = it * 8 + w;           // item id 0..103; uniform across warp
        uint2 v = __ldg(tn2 + sidx[g] + lane);
        int d = __dp4a((int)v.x, (int)q.x, __dp4a((int)v.y, (int)q.y, 0));
        if (g < 101) sp[g * 36 + lane] = d;   // warp-uniform predicate
    }
    __syncthreads();

    // Reduce 32 int partials per item with LDS.128 (thread i -> item i).
    // 144B rows: 8 consecutive threads' int4 loads cover all 32 banks.
    if (tid < 101) {
        const int4* r4 = reinterpret_cast<const int4*>(sp + tid * 36);
        int4 a0 = r4[0], a1 = r4[1], a2 = r4[2], a3 = r4[3];
        int4 a4 = r4[4], a5 = r4[5], a6 = r4[6], a7 = r4[7];
        int s0 = (a0.x + a0.y) + (a0.z + a0.w);
        int s1 = (a1.x + a1.y) + (a1.z + a1.w);
        int s2 = (a2.x + a2.y) + (a2.z + a2.w);
        int s3 = (a3.x + a3.y) + (a3.z + a3.w);
        int s4 = (a4.x + a4.y) + (a4.z + a4.w);
        int s5 = (a5.x + a5.y) + (a5.z + a5.w);
        int s6 = (a6.x + a6.y) + (a6.z + a6.w);
        int s7 = (a7.x + a7.y) + (a7.z + a7.w);
        int tot = (((s0 + s1) + (s2 + s3)) + ((s4 + s5) + (s6 + s7)));
        logits[tid] = (float)tot * (10.0f / 16129.0f);   // /TEMP / 127^2
    }
    __syncthreads();

    if (w == 0) {
        float mx = -1e30f;
        for (int i = lane; i < 101; i += 32) mx = fmaxf(mx, logits[i]);
        mx = wmax(mx);
        float sum = 0.0f;
        for (int i = lane; i < 101; i += 32) sum += __expf(logits[i] - mx);
        sum = wsum(sum);
        if (lane == 0) {
            float lse = mx + __logf(sum);
            g_part[(size_t)(s - 1) * MROWS + bt] =
                (lse - logits[0]) / (float)(NSTEP * BATCH * T2);
        }
    }
}

// ---------------------------------------------------------------------------
// Kernel 5: deterministic final reduction
// ---------------------------------------------------------------------------
__global__ void k_reduce(float* __restrict__ out) {
    __shared__ float sm[256];
    int tid = threadIdx.x;
    float s = 0.0f;
    for (int i = tid; i < NSTEP * MROWS; i += 256) s += g_part[i];
    sm[tid] = s;
    __syncthreads();
    for (int o = 128; o; o >>= 1) {
        if (tid < o) sm[tid] += sm[tid + o];
        __syncthreads();
    }
    if (tid == 0) out[0] = sm[0];
}

// ---------------------------------------------------------------------------
extern "C" void kernel_launch(void* const* d_in, const int* in_sizes, int n_in,
                              void* d_out, int out_size) {
    const float* ctx  = (const float*)d_in[0];
    const float* tgt  = (const float*)d_in[1];
    const float* W    = (const float*)d_in[2];
    const float* bias = (const float*)d_in[3];
    float* out = (float*)d_out;

    uint32_t* abf;  cudaGetSymbolAddress((void**)&abf, g_Abf);
    uint32_t* bbf;  cudaGetSymbolAddress((void**)&bbf, g_Bbf);

    k_norm_targets<<<(BATCH * TLEN) / 8, 256>>>(tgt);
    k_cvt<<<(MROWS * DIM / 2) / 256, 256>>>((const float2*)ctx, abf, MROWS * DIM / 2);
    k_cvt<<<(NCOLS * DIM / 2) / 256, 256>>>((const float2*)W, bbf, NCOLS * DIM / 2);
    k_mma<<<dim3(NCOLS / 128, MROWS / 128), 256>>>();
    k_bias_norm<<<(MROWS * NSTEP) / 8, 256>>>(bias);
    k_loss<<<dim3(MROWS, NSTEP), 256>>>();
    k_reduce<<<1, 256>>>(out);
}

// round 16
// speedup vs baseline: 2.0492x; 1.0003x over previous
#include <cuda_runtime.h>
#include <cuda_bf16.h>
#include <cstdint>

#define BATCH 8
#define TLEN 256
#define DIM 256
#define NSTEP 12
#define NNEG 100
#define MROWS 2048
#define NCOLS 3072

__device__ float g_C[MROWS * NCOLS];                 // raw GEMM output (f32)
__device__ uint32_t g_tn8[MROWS * 64];               // normalized targets, s8x4
__device__ float g_part[NSTEP * MROWS];              // per-sample loss partials
__device__ uint32_t g_Abf[MROWS * DIM / 2];          // ctx in bf16x2, k-major
__device__ uint32_t g_Bbf[NCOLS * DIM / 2];          // W   in bf16x2, k-major

// ---------------------------------------------------------------------------
// warp reductions (butterfly shfl — f32 redux does NOT exist on sm_103a)
// ---------------------------------------------------------------------------
__device__ __forceinline__ float wsum(float v) {
#pragma unroll
    for (int o = 16; o; o >>= 1) v += __shfl_xor_sync(0xffffffffu, v, o);
    return v;
}
__device__ __forceinline__ float wmax(float v) {
#pragma unroll
    for (int o = 16; o; o >>= 1) v = fmaxf(v, __shfl_xor_sync(0xffffffffu, v, o));
    return v;
}

// ---------------------------------------------------------------------------
// Threefry-2x32 (exact JAX rotation/key schedule)
// ---------------------------------------------------------------------------
__device__ __forceinline__ void tf2x32(uint32_t k0, uint32_t k1,
                                       uint32_t x0, uint32_t x1,
                                       uint32_t &o0, uint32_t &o1) {
    uint32_t ks2 = k0 ^ k1 ^ 0x1BD11BDAu;
    x0 += k0; x1 += k1;
#define TFR(r) { x0 += x1; x1 = __funnelshift_l(x1, x1, (r)); x1 ^= x0; }
    TFR(13) TFR(15) TFR(26) TFR(6)   x0 += k1;  x1 += ks2 + 1u;
    TFR(17) TFR(29) TFR(16) TFR(24)  x0 += ks2; x1 += k0 + 2u;
    TFR(13) TFR(15) TFR(26) TFR(6)   x0 += k0;  x1 += k1 + 3u;
    TFR(17) TFR(29) TFR(16) TFR(24)  x0 += k1;  x1 += ks2 + 4u;
    TFR(13) TFR(15) TFR(26) TFR(6)   x0 += ks2; x1 += k0 + 5u;
#undef TFR
    o0 = x0; o1 = x1;
}

__device__ __forceinline__ uint32_t tf_bits32(uint32_t k0, uint32_t k1, uint32_t i) {
    uint32_t a, b;
    tf2x32(k0, k1, 0u, i, a, b);
    return a ^ b;
}

// ---------------------------------------------------------------------------
// bf16x2 / int8 helpers
// ---------------------------------------------------------------------------
__device__ __forceinline__ uint32_t f2_to_bf2(float lo, float hi) {
    __nv_bfloat162 p = __floats2bfloat162_rn(lo, hi);   // .x = lo (low half)
    return *reinterpret_cast<uint32_t*>(&p);
}
// pack 4 floats (already scaled to [-127,127]) as s8x4
__device__ __forceinline__ uint32_t pack_s8x4(float a, float b, float c, float d) {
    int ia = __float2int_rn(a), ib = __float2int_rn(b);
    int ic = __float2int_rn(c), id = __float2int_rn(d);
    return (uint32_t)(ia & 0xff) | ((uint32_t)(ib & 0xff) << 8) |
           ((uint32_t)(ic & 0xff) << 16) | ((uint32_t)(id & 0xff) << 24);
}

// ---------------------------------------------------------------------------
// async copy / ldmatrix / mma primitives
// ---------------------------------------------------------------------------
__device__ __forceinline__ void cpa16(uint32_t dst, const void* src) {
    asm volatile("cp.async.cg.shared.global [%0], [%1], 16;"
                 :: "r"(dst), "l"(src));
}
__device__ __forceinline__ void ldsm4(uint32_t &r0, uint32_t &r1,
                                      uint32_t &r2, uint32_t &r3, uint32_t a) {
    asm volatile("ldmatrix.sync.aligned.m8n8.x4.shared.b16 {%0,%1,%2,%3}, [%4];"
                 : "=r"(r0), "=r"(r1), "=r"(r2), "=r"(r3) : "r"(a));
}
__device__ __forceinline__ void mma_bf16(float* d, const uint32_t* a,
                                         uint32_t b0, uint32_t b1) {
    asm("mma.sync.aligned.m16n8k16.row.col.f32.bf16.bf16.f32 "
        "{%0,%1,%2,%3}, {%4,%5,%6,%7}, {%8,%9}, {%0,%1,%2,%3};"
        : "+f"(d[0]), "+f"(d[1]), "+f"(d[2]), "+f"(d[3])
        : "r"(a[0]), "r"(a[1]), "r"(a[2]), "r"(a[3]), "r"(b0), "r"(b1));
}

// ---------------------------------------------------------------------------
// Kernel 1 (fused prep): blockIdx branches over three independent jobs:
//   [0,256)        normalize target rows -> s8 (uniform scale 127)
//   [256,1280)     ctx  fp32 -> bf16x2
//   [1280,2816)    W    fp32 -> bf16x2
// ---------------------------------------------------------------------------
__global__ __launch_bounds__(256) void k_prep(const float* __restrict__ tgt,
                                              const float* __restrict__ ctx,
                                              const float* __restrict__ W) {
    int blk = blockIdx.x;
    int tid = threadIdx.x;
    if (blk < 256) {
        int gw = blk * 8 + (tid >> 5);            // target row 0..2047
        int lane = tid & 31;
        const float4* r = reinterpret_cast<const float4*>(tgt + (size_t)gw * DIM);
        float4 a = r[lane * 2];
        float4 b = r[lane * 2 + 1];
        float ss = a.x*a.x + a.y*a.y + a.z*a.z + a.w*a.w
                 + b.x*b.x + b.y*b.y + b.z*b.z + b.w*b.w;
        ss = wsum(ss);
        float q = 127.0f / fmaxf(sqrtf(ss), 1e-12f);
        uint2 u;
        u.x = pack_s8x4(a.x * q, a.y * q, a.z * q, a.w * q);
        u.y = pack_s8x4(b.x * q, b.y * q, b.z * q, b.w * q);
        reinterpret_cast<uint2*>(g_tn8 + (size_t)gw * 64)[lane] = u;
    } else if (blk < 1280) {
        int i = (blk - 256) * 256 + tid;          // ctx pair index
        float2 v = reinterpret_cast<const float2*>(ctx)[i];
        g_Abf[i] = f2_to_bf2(v.x, v.y);
    } else {
        int i = (blk - 1280) * 256 + tid;         // W pair index
        float2 v = reinterpret_cast<const float2*>(W)[i];
        g_Bbf[i] = f2_to_bf2(v.x, v.y);
    }
}

// ---------------------------------------------------------------------------
// Kernel 2: C[2048,3072] = A[2048,256] * B[3072,256]^T via smem-tiled HMMA.
//   Block tile 128x128, 8 warps (warp = 32x64), K chunks of 32, double-
//   buffered cp.async.cg, fragments via ldmatrix.x4. Smem rows padded to
//   80B -> LDSM 8-row address sets hit 8 distinct 16B slots (conflict-free).
// ---------------------------------------------------------------------------
#define KCHUNKS 8
#define ROWB 80                      // padded row stride in bytes (32 bf16 + pad)
#define TILEB (128 * ROWB)           // 10240 B per tile buffer

__global__ __launch_bounds__(256) void k_mma() {
    __shared__ uint8_t sA[2][TILEB];
    __shared__ uint8_t sB[2][TILEB];

    int tid = threadIdx.x;
    int lane = tid & 31, w = tid >> 5;
    int bm = blockIdx.y * 128;       // M block
    int bn = blockIdx.x * 128;       // N block
    int wmo = (w & 3) * 32;          // warp m-offset in tile
    int wno = (w >> 2) * 64;         // warp n-offset in tile

    uint32_t sAu = (uint32_t)__cvta_generic_to_shared(&sA[0][0]);
    uint32_t sBu = (uint32_t)__cvta_generic_to_shared(&sB[0][0]);

    // copy indexing: 2 rows per thread per tile (128 rows x 4 segs of 16B)
    int crow = tid >> 2, cseg = tid & 3;
    const uint32_t* gA = g_Abf + (size_t)(bm + crow) * 128 + cseg * 4;
    const uint32_t* gB = g_Bbf + (size_t)(bn + crow) * 128 + cseg * 4;
    uint32_t dA = sAu + crow * ROWB + cseg * 16;
    uint32_t dB = sBu + crow * ROWB + cseg * 16;

#define COPY_CHUNK(c, buf)                                                    \
    {                                                                         \
        cpa16(dA + (buf) * TILEB, gA + (c) * 16);                             \
        cpa16(dA + (buf) * TILEB + 64 * ROWB, gA + 64 * 128 + (c) * 16);      \
        cpa16(dB + (buf) * TILEB, gB + (c) * 16);                            \
        cpa16(dB + (buf) * TILEB + 64 * ROWB, gB + 64 * 128 + (c) * 16);      \
        asm volatile("cp.async.commit_group;");                               \
    }

    float acc[2][8][4];
#pragma unroll
    for (int i = 0; i < 2; i++)
#pragma unroll
        for (int j = 0; j < 8; j++)
#pragma unroll
            for (int k = 0; k < 4; k++) acc[i][j][k] = 0.0f;

    int gh = (lane >> 3) & 1;        // ldmatrix address group: row half
    int kh = lane >> 4;              // ldmatrix address group: k half
    int lr = lane & 7;               // row within 8
    int qr = lane >> 2, kc = lane & 3;

    COPY_CHUNK(0, 0)

    for (int c = 0; c < KCHUNKS; c++) {
        int buf = c & 1;
        if (c < KCHUNKS - 1) COPY_CHUNK(c + 1, buf ^ 1)
        if (c < KCHUNKS - 1) asm volatile("cp.async.wait_group 1;");
        else                 asm volatile("cp.async.wait_group 0;");
        __syncthreads();

        uint32_t aBase = sAu + buf * TILEB;
        uint32_t bBase = sBu + buf * TILEB;
#pragma unroll
        for (int c16 = 0; c16 < 2; c16++) {
            uint32_t kbyte = c16 * 32 + kh * 16;
            uint32_t a[2][4];
#pragma unroll
            for (int mf = 0; mf < 2; mf++) {
                uint32_t addr = aBase + (wmo + mf * 16 + gh * 8 + lr) * ROWB + kbyte;
                ldsm4(a[mf][0], a[mf][1], a[mf][2], a[mf][3], addr);
            }
#pragma unroll
            for (int nfp = 0; nfp < 4; nfp++) {
                uint32_t b0, b1, b2, b3;
                uint32_t addr = bBase + (wno + nfp * 16 + gh * 8 + lr) * ROWB + kbyte;
                ldsm4(b0, b1, b2, b3, addr);
                mma_bf16(acc[0][nfp * 2],     a[0], b0, b2);
                mma_bf16(acc[0][nfp * 2 + 1], a[0], b1, b3);
                mma_bf16(acc[1][nfp * 2],     a[1], b0, b2);
                mma_bf16(acc[1][nfp * 2 + 1], a[1], b1, b3);
            }
        }
        __syncthreads();
    }
#undef COPY_CHUNK

    // Epilogue: D row r: c0,c1 at (qr, 2kc); c2,c3 at row +8. float2 stores.
#pragma unroll
    for (int mf = 0; mf < 2; mf++) {
#pragma unroll
        for (int nf = 0; nf < 8; nf++) {
            float* d = acc[mf][nf];
            int r = bm + wmo + mf * 16 + qr;
            int cc = bn + wno + nf * 8 + kc * 2;
            *reinterpret_cast<float2*>(g_C + (size_t)r * NCOLS + cc) =
                make_float2(d[0], d[1]);
            *reinterpret_cast<float2*>(g_C + (size_t)(r + 8) * NCOLS + cc) =
                make_float2(d[2], d[3]);
        }
    }
}

// ---------------------------------------------------------------------------
// Kernel 3: per-(step,b,t) InfoNCE partial loss with FUSED query prep.
//   Prologue: block reads its own f32 query row from g_C (1KB), adds bias,
//   block-reduces the L2 norm, quantizes to s8 in smem (the row is consumed
//   by exactly this block — no reuse, so no separate materialization pass).
//   Mainloop: warp-per-item s8 gather (256B rows), 2 DP4A/lane, exact int32
//   partials, LDS.128 reduce, fully unrolled (MLP ~13).
// ---------------------------------------------------------------------------
__global__ __launch_bounds__(256) void k_loss(const float* __restrict__ bias) {
    int s = blockIdx.y + 1;           // step 1..12
    int T2 = TLEN - s;
    int bt = blockIdx.x;              // 0..2047
    int b = bt >> 8, t = bt & 255;
    int tid = threadIdx.x;
    __shared__ __align__(16) int sp[101 * 36];  // per-lane int partials
    __shared__ float logits[101];
    __shared__ int sidx[104];         // row * 32 (uint2 units); 101..103 = pad
    __shared__ uint32_t cst[3];       // k0, k1, mult
    __shared__ float snorm[9];        // 8 warp sums + inv-scale
    __shared__ __align__(8) int8_t sq8[256];    // quantized query row
    if (t >= T2) {
        if (tid == 0) g_part[(size_t)(s - 1) * MROWS + bt] = 0.0f;
        return;
    }
    int lane = tid & 31, w = tid >> 5;
    uint32_t span = (uint32_t)(BATCH * T2);

    // --- phase 0: PRNG constants + per-thread query element & warp sq-sums
    float qv = g_C[(size_t)bt * NCOLS + (size_t)(s - 1) * DIM + tid]
             + bias[(size_t)(s - 1) * DIM + tid];
    float ssq = wsum(qv * qv);
    if (lane == 0) snorm[w] = ssq;
    if (tid == 0) {
        uint32_t k0, k1;
        tf2x32(0u, 1234u, 0u, (uint32_t)s, k0, k1);   // fold_in(key(1234), s)
        uint32_t m16 = 65536u % span;
        cst[0] = k0; cst[1] = k1; cst[2] = (m16 * m16) % span;
    }
    __syncthreads();

    // --- phase 1: negative indices (threads 0..103) + norm finalize (tid 0)
    if (tid < 104) {
        int row = 0;                  // pad rows -> row 0 (discarded)
        if (tid == 0) {
            row = b * TLEN + t + s;   // positive
        } else if (tid < 101) {
            uint32_t k0 = cst[0], k1 = cst[1], mult = cst[2];
            uint32_t n = span * NNEG;
            uint32_t i = (uint32_t)((b * T2 + t) * NNEG + (tid - 1));
            uint32_t hi = tf_bits32(k0, k1, i);
            uint32_t lo = tf_bits32(k0, k1, n + i);
            uint32_t off = ((hi % span) * mult + (lo % span)) % span;
            uint32_t b2 = off / (uint32_t)T2;
            uint32_t t2 = off - b2 * (uint32_t)T2;
            row = (int)(b2 * TLEN + (uint32_t)s + t2);
        }
        sidx[tid] = row * 32;
    }
    if (tid == 224) {                 // a warp not busy with sidx
        float tot = ((snorm[0] + snorm[1]) + (snorm[2] + snorm[3]))
                  + ((snorm[4] + snorm[5]) + (snorm[6] + snorm[7]));
        snorm[8] = 127.0f / fmaxf(sqrtf(tot), 1e-12f);
    }
    __syncthreads();

    // --- phase 2: quantize query row into smem
    sq8[tid] = (int8_t)__float2int_rn(qv * snorm[8]);
    __syncthreads();

    // --- phase 3: gather + dot mainloop
    uint2 q = reinterpret_cast<const uint2*>(sq8)[lane];
    const uint2* tn2 = reinterpret_cast<const uint2*>(g_tn8);
#pragma unroll
    for (int it = 0; it < 13; it++) {
        int g = it * 8 + w;           // item id 0..103; uniform across warp
        uint2 v = __ldg(tn2 + sidx[g] + lane);
        int d = __dp4a((int)v.x, (int)q.x, __dp4a((int)v.y, (int)q.y, 0));
        if (g < 101) sp[g * 36 + lane] = d;   // warp-uniform predicate
    }
    __syncthreads();

    // --- phase 4: reduce 32 int partials per item with LDS.128
    if (tid < 101) {
        const int4* r4 = reinterpret_cast<const int4*>(sp + tid * 36);
        int4 a0 = r4[0], a1 = r4[1], a2 = r4[2], a3 = r4[3];
        int4 a4 = r4[4], a5 = r4[5], a6 = r4[6], a7 = r4[7];
        int s0 = (a0.x + a0.y) + (a0.z + a0.w);
        int s1 = (a1.x + a1.y) + (a1.z + a1.w);
        int s2 = (a2.x + a2.y) + (a2.z + a2.w);
        int s3 = (a3.x + a3.y) + (a3.z + a3.w);
        int s4 = (a4.x + a4.y) + (a4.z + a4.w);
        int s5 = (a5.x + a5.y) + (a5.z + a5.w);
        int s6 = (a6.x + a6.y) + (a6.z + a6.w);
        int s7 = (a7.x + a7.y) + (a7.z + a7.w);
        int tot = (((s0 + s1) + (s2 + s3)) + ((s4 + s5) + (s6 + s7)));
        logits[tid] = (float)tot * (10.0f / 16129.0f);   // /TEMP / 127^2
    }
    __syncthreads();

    // --- phase 5: log-softmax + partial write
    if (w == 0) {
        float mx = -1e30f;
        for (int i = lane; i < 101; i += 32) mx = fmaxf(mx, logits[i]);
        mx = wmax(mx);
        float sum = 0.0f;
        for (int i = lane; i < 101; i += 32) sum += __expf(logits[i] - mx);
        sum = wsum(sum);
        if (lane == 0) {
            float lse = mx + __logf(sum);
            g_part[(size_t)(s - 1) * MROWS + bt] =
                (lse - logits[0]) / (float)(NSTEP * BATCH * T2);
        }
    }
}

// ---------------------------------------------------------------------------
// Kernel 4: deterministic final reduction
// ---------------------------------------------------------------------------
__global__ void k_reduce(float* __restrict__ out) {
    __shared__ float sm[256];
    int tid = threadIdx.x;
    float s = 0.0f;
    for (int i = tid; i < NSTEP * MROWS; i += 256) s += g_part[i];
    sm[tid] = s;
    __syncthreads();
    for (int o = 128; o; o >>= 1) {
        if (tid < o) sm[tid] += sm[tid + o];
        __syncthreads();
    }
    if (tid == 0) out[0] = sm[0];
}

// ---------------------------------------------------------------------------
extern "C" void kernel_launch(void* const* d_in, const int* in_sizes, int n_in,
                              void* d_out, int out_size) {
    const float* ctx  = (const float*)d_in[0];
    const float* tgt  = (const float*)d_in[1];
    const float* W    = (const float*)d_in[2];
    const float* bias = (const float*)d_in[3];
    float* out = (float*)d_out;

    k_prep<<<2816, 256>>>(tgt, ctx, W);
    k_mma<<<dim3(NCOLS / 128, MROWS / 128), 256>>>();
    k_loss<<<dim3(MROWS, NSTEP), 256>>>(bias);
    k_reduce<<<1, 256>>>(out);
}